// round 1
// baseline (speedup 1.0000x reference)
#include <cuda_runtime.h>
#include <math.h>

// Problem constants
#define TT  30
#define BBN 2048
#define DD  256
#define DHH 128

// Scratch (device globals — no allocation allowed)
__device__ float g_repT[DHH * BBN];             // rep transposed [k][c]
__device__ float g_A29T[DHH * BBN];             // A for t=29, transposed [h][b]
__device__ float g_lse29[BBN];                  // row logsumexp for t=29
__device__ float g_nce[TT * 16];                // per-(t,rowblock) partial sums of diag logp
__device__ unsigned long long g_win[BBN];       // per-column packed (score,idx) winners

#define LDT 132                                  // padded smem row stride (floats)
#define SMEM_MAIN ((2 * 128 * LDT + 128 + 16) * 4)
#define SMEM_ACC  ((2 * 128 * LDT) * 4)

// ---------------------------------------------------------------------------
// Pre-pass: transpose rep into [k][c] layout, zero the argmax winners
// ---------------------------------------------------------------------------
__global__ void k_pre(const float* __restrict__ rep) {
    int idx = blockIdx.x * blockDim.x + threadIdx.x;   // 0 .. 2048*128-1
    int c = idx >> 7;
    int k = idx & 127;
    g_repT[k * BBN + c] = rep[idx];
    if (idx < BBN) g_win[idx] = 0ULL;
}

// ---------------------------------------------------------------------------
// Main fused kernel: per (t, 128-row block)
//   phase 1: A_tile[128x128] = E_t[rows,256] @ W_t[256,128]
//   phase 2: stream 16 column tiles of rep, S = A @ rep^T with online softmax
//            (row max / sum-exp), capture diagonal, emit nce partial.
//   For t == 29 additionally store A tile (transposed) and row lse to global.
// ---------------------------------------------------------------------------
__global__ void __launch_bounds__(256, 1)
k_main(const float* __restrict__ E, const float* __restrict__ W) {
    extern __shared__ float sm[];
    float* sAT   = sm;                  // [128][LDT]  A transposed: [h][b]
    float* sX    = sm + 128 * LDT;      // phase1: sE + sW   / phase2: sR
    float* sE    = sX;                  // [128][36]
    float* sW    = sX + 128 * 36;       // [32][LDT]
    float* sR    = sX;                  // [128][LDT]  repT tile: [k][c]
    float* sDiag = sm + 2 * 128 * LDT;  // [128]
    float* sRed  = sDiag + 128;         // [16]

    const int t      = blockIdx.y;
    const int rb     = blockIdx.x;
    const int base_b = rb * 128;
    const int tid    = threadIdx.x;
    const int tx     = tid & 15;
    const int ty     = tid >> 4;

    const float* Et = E + (size_t)t * BBN * DD;
    const float* Wt = W + (size_t)t * DD * DHH;

    float acc[8][8];
#pragma unroll
    for (int i = 0; i < 8; ++i)
#pragma unroll
        for (int j = 0; j < 8; ++j) acc[i][j] = 0.0f;

    // ---------------- Phase 1: A tile = E @ W ----------------
    for (int dk = 0; dk < DD; dk += 32) {
        __syncthreads();
        {   // load E chunk [128 rows x 32 k] -> sE[r][kk]
            int qk = tid & 7;
            int r0 = tid >> 3;
#pragma unroll
            for (int it = 0; it < 4; ++it) {
                int r = r0 + it * 32;
                float4 v = *(const float4*)(Et + (size_t)(base_b + r) * DD + dk + qk * 4);
                *(float4*)(sE + r * 36 + qk * 4) = v;
            }
        }
        {   // load W chunk [32 k x 128 h] -> sW[kk][h]
            int q   = tid & 31;
            int kk0 = tid >> 5;
#pragma unroll
            for (int it = 0; it < 4; ++it) {
                int kk = kk0 + it * 8;
                float4 v = *(const float4*)(Wt + (size_t)(dk + kk) * DHH + q * 4);
                *(float4*)(sW + kk * LDT + q * 4) = v;
            }
        }
        __syncthreads();
#pragma unroll 4
        for (int kd = 0; kd < 32; ++kd) {
            float a[8], b[8];
#pragma unroll
            for (int i = 0; i < 8; ++i) a[i] = sE[(ty * 8 + i) * 36 + kd];
            float4 b0 = *(const float4*)(sW + kd * LDT + tx * 8);
            float4 b1 = *(const float4*)(sW + kd * LDT + tx * 8 + 4);
            b[0] = b0.x; b[1] = b0.y; b[2] = b0.z; b[3] = b0.w;
            b[4] = b1.x; b[5] = b1.y; b[6] = b1.z; b[7] = b1.w;
#pragma unroll
            for (int i = 0; i < 8; ++i)
#pragma unroll
                for (int j = 0; j < 8; ++j)
                    acc[i][j] = fmaf(a[i], b[j], acc[i][j]);
        }
    }
    __syncthreads();

    // store A tile transposed into smem: sAT[h][b_local]
#pragma unroll
    for (int j = 0; j < 8; ++j)
#pragma unroll
        for (int i = 0; i < 8; ++i)
            sAT[(tx * 8 + j) * LDT + ty * 8 + i] = acc[i][j];

    if (t == TT - 1) {   // save A for the accuracy pass (transposed [h][b])
#pragma unroll
        for (int j = 0; j < 8; ++j)
#pragma unroll
            for (int i = 0; i < 8; ++i)
                g_A29T[(size_t)(tx * 8 + j) * BBN + base_b + ty * 8 + i] = acc[i][j];
    }
    __syncthreads();

    // ---------------- Phase 2: S = A @ rep^T with online softmax ----------
    const float NEGINF = __int_as_float(0xff800000);
    float m[8], s[8];
#pragma unroll
    for (int i = 0; i < 8; ++i) { m[i] = NEGINF; s[i] = 0.0f; }

    for (int ct = 0; ct < 16; ++ct) {
        __syncthreads();
        {   // load rep tile [k 0..127][c ct*128..+127] from g_repT (coalesced)
            int q  = tid & 31;
            int k0 = tid >> 5;
#pragma unroll
            for (int it = 0; it < 16; ++it) {
                int k = k0 + it * 8;
                *(float4*)(sR + k * LDT + q * 4) =
                    *(const float4*)(g_repT + (size_t)k * BBN + ct * 128 + q * 4);
            }
        }
        __syncthreads();

#pragma unroll
        for (int i = 0; i < 8; ++i)
#pragma unroll
            for (int j = 0; j < 8; ++j) acc[i][j] = 0.0f;

#pragma unroll 4
        for (int kd = 0; kd < 128; ++kd) {
            float4 a0 = *(const float4*)(sAT + kd * LDT + ty * 8);
            float4 a1 = *(const float4*)(sAT + kd * LDT + ty * 8 + 4);
            float4 b0 = *(const float4*)(sR  + kd * LDT + tx * 8);
            float4 b1 = *(const float4*)(sR  + kd * LDT + tx * 8 + 4);
            float a[8] = {a0.x, a0.y, a0.z, a0.w, a1.x, a1.y, a1.z, a1.w};
            float b[8] = {b0.x, b0.y, b0.z, b0.w, b1.x, b1.y, b1.z, b1.w};
#pragma unroll
            for (int i = 0; i < 8; ++i)
#pragma unroll
                for (int j = 0; j < 8; ++j)
                    acc[i][j] = fmaf(a[i], b[j], acc[i][j]);
        }

        // capture diagonal (column block == row block, thread-diagonal only)
        if (ct == rb && tx == ty) {
#pragma unroll
            for (int i = 0; i < 8; ++i) sDiag[ty * 8 + i] = acc[i][i];
        }

        // online softmax update for the 8 rows this thread shares with its tx-group
#pragma unroll
        for (int i = 0; i < 8; ++i) {
            float tmax = acc[i][0];
#pragma unroll
            for (int j = 1; j < 8; ++j) tmax = fmaxf(tmax, acc[i][j]);
#pragma unroll
            for (int msk = 1; msk < 16; msk <<= 1)
                tmax = fmaxf(tmax, __shfl_xor_sync(0xffffffffu, tmax, msk));
            float nm = fmaxf(m[i], tmax);
            float p = 0.0f;
#pragma unroll
            for (int j = 0; j < 8; ++j) p += __expf(acc[i][j] - nm);
#pragma unroll
            for (int msk = 1; msk < 16; msk <<= 1)
                p += __shfl_xor_sync(0xffffffffu, p, msk);
            s[i] = fmaf(s[i], __expf(m[i] - nm), p);
            m[i] = nm;
        }
    }
    __syncthreads();   // make sDiag visible to everyone

    if (tx == 0) {
        float part = 0.0f;
#pragma unroll
        for (int i = 0; i < 8; ++i) {
            float lse = m[i] + __logf(s[i]);
            part += sDiag[ty * 8 + i] - lse;
            if (t == TT - 1) g_lse29[base_b + ty * 8 + i] = lse;
        }
        sRed[ty] = part;
    }
    __syncthreads();
    if (tid == 0) {
        float tot = 0.0f;
        for (int r = 0; r < 16; ++r) tot += sRed[r];
        g_nce[t * 16 + rb] = tot;
    }
}

// ---------------------------------------------------------------------------
// Accuracy pass (t = 29): per column c, argmax over b of (S[b,c] - lse[b]).
// Tile [128 c x 128 b] per CTA; combine across b-blocks via packed atomicMax.
// ---------------------------------------------------------------------------
__global__ void __launch_bounds__(256, 1)
k_acc() {
    extern __shared__ float sm[];
    float* sRc = sm;                 // [k][c] rep tile
    float* sAb = sm + 128 * LDT;     // [k][b] A29 tile

    const int cb  = blockIdx.x;      // column block
    const int bb  = blockIdx.y;      // row (b) block
    const int tid = threadIdx.x;
    const int tx  = tid & 15;
    const int ty  = tid >> 4;

    {
        int q  = tid & 31;
        int k0 = tid >> 5;
#pragma unroll
        for (int it = 0; it < 16; ++it) {
            int k = k0 + it * 8;
            *(float4*)(sRc + k * LDT + q * 4) =
                *(const float4*)(g_repT + (size_t)k * BBN + cb * 128 + q * 4);
            *(float4*)(sAb + k * LDT + q * 4) =
                *(const float4*)(g_A29T + (size_t)k * BBN + bb * 128 + q * 4);
        }
    }
    __syncthreads();

    float acc[8][8];
#pragma unroll
    for (int i = 0; i < 8; ++i)
#pragma unroll
        for (int j = 0; j < 8; ++j) acc[i][j] = 0.0f;

#pragma unroll 4
    for (int kd = 0; kd < 128; ++kd) {
        float4 a0 = *(const float4*)(sRc + kd * LDT + ty * 8);
        float4 a1 = *(const float4*)(sRc + kd * LDT + ty * 8 + 4);
        float4 b0 = *(const float4*)(sAb + kd * LDT + tx * 8);
        float4 b1 = *(const float4*)(sAb + kd * LDT + tx * 8 + 4);
        float a[8] = {a0.x, a0.y, a0.z, a0.w, a1.x, a1.y, a1.z, a1.w};
        float b[8] = {b0.x, b0.y, b0.z, b0.w, b1.x, b1.y, b1.z, b1.w};
#pragma unroll
        for (int i = 0; i < 8; ++i)
#pragma unroll
            for (int j = 0; j < 8; ++j)
                acc[i][j] = fmaf(a[i], b[j], acc[i][j]);
    }

    float lse[8];
#pragma unroll
    for (int j = 0; j < 8; ++j) lse[j] = g_lse29[bb * 128 + tx * 8 + j];

#pragma unroll
    for (int i = 0; i < 8; ++i) {
        unsigned long long best = 0ULL;
#pragma unroll
        for (int j = 0; j < 8; ++j) {
            float v = acc[i][j] - lse[j];
            unsigned u = __float_as_uint(v);
            u = (u & 0x80000000u) ? ~u : (u | 0x80000000u);
            unsigned long long key =
                ((unsigned long long)u << 32) | (unsigned)(bb * 128 + tx * 8 + j);
            if (key > best) best = key;
        }
#pragma unroll
        for (int msk = 1; msk < 16; msk <<= 1) {
            unsigned long long o = __shfl_xor_sync(0xffffffffu, best, msk);
            if (o > best) best = o;
        }
        if (tx == 0)
            atomicMax(&g_win[cb * 128 + ty * 8 + i], best);
    }
}

// ---------------------------------------------------------------------------
// Finalize: count argmax matches, reduce nce partials, write outputs.
// ---------------------------------------------------------------------------
__global__ void k_fin(float* __restrict__ out, int out_size) {
    __shared__ double rd[256];
    __shared__ int    ri[256];
    int tid = threadIdx.x;

    int cnt = 0;
    for (int c = tid; c < BBN; c += 256)
        cnt += ((unsigned)(g_win[c] & 0xffffffffULL) == (unsigned)c);

    double sum = 0.0;
    for (int i = tid; i < TT * 16; i += 256) sum += (double)g_nce[i];

    rd[tid] = sum; ri[tid] = cnt;
    __syncthreads();
    for (int st = 128; st > 0; st >>= 1) {
        if (tid < st) { rd[tid] += rd[tid + st]; ri[tid] += ri[tid + st]; }
        __syncthreads();
    }
    if (tid == 0) {
        out[0] = (float)ri[0] / (float)BBN;                    // accuracy
        out[1] = (float)(rd[0] / (-(double)(BBN * TT)));       // nce
        out[2] = (float)BBN;                                   // batch
        out[3] = (float)(BBN * TT);                            // calc_step
        for (int i = 4; i < out_size; ++i) out[i] = 0.0f;
    }
}

// ---------------------------------------------------------------------------
extern "C" void kernel_launch(void* const* d_in, const int* in_sizes, int n_in,
                              void* d_out, int out_size) {
    const float* E   = (const float*)d_in[0];   // [30, 2048, 256]
    const float* rep = (const float*)d_in[1];   // [2048, 128]
    const float* W   = (const float*)d_in[2];   // [30, 256, 128]
    // d_in[3] = Wk_b: provably irrelevant (row-constant shift, cancels in softmax)
    float* out = (float*)d_out;

    cudaFuncSetAttribute(k_main, cudaFuncAttributeMaxDynamicSharedMemorySize, SMEM_MAIN);
    cudaFuncSetAttribute(k_acc,  cudaFuncAttributeMaxDynamicSharedMemorySize, SMEM_ACC);

    k_pre<<<(BBN * DHH) / 256, 256>>>(rep);

    dim3 g2(16, TT);
    k_main<<<g2, 256, SMEM_MAIN>>>(E, W);

    dim3 g3(16, 16);
    k_acc<<<g3, 256, SMEM_ACC>>>();

    k_fin<<<1, 256>>>(out, out_size);
}

// round 2
// speedup vs baseline: 1.0800x; 1.0800x over previous
#include <cuda_runtime.h>
#include <math.h>

#define TT  30
#define BBN 2048
#define DD  256
#define DHH 128

// Scratch (device globals — no allocation allowed)
__device__ float g_repT[DHH * BBN];             // rep transposed [k][c]
__device__ float g_A29T[DHH * BBN];             // A for t=29, transposed [h][b]
__device__ float g_lse29[BBN];                  // row logsumexp for t=29
__device__ float g_nce[TT * 16];                // per-(t,rowblock) diag-logp partials
__device__ unsigned long long g_win[BBN];       // per-column packed (score,idx) winners

#define LDT  132                                 // sAT / sW row stride (floats)
#define LDC2 264                                 // sR row stride (floats), 256-wide tile
#define SMEM_MAIN ((128 * LDT + 128 * LDC2 + 128 + 8) * 4)
#define SMEM_ACC  ((2 * 128 * LDT) * 4)

typedef unsigned long long u64;

__device__ __forceinline__ u64 pk2(float f) {
    u64 r; asm("mov.b64 %0, {%1, %1};" : "=l"(r) : "f"(f)); return r;
}
__device__ __forceinline__ void upk(u64 v, float& lo, float& hi) {
    asm("mov.b64 {%0, %1}, %2;" : "=f"(lo), "=f"(hi) : "l"(v));
}
__device__ __forceinline__ u64 ffma2(u64 a, u64 b, u64 c) {
    u64 d; asm("fma.rn.f32x2 %0, %1, %2, %3;" : "=l"(d) : "l"(a), "l"(b), "l"(c));
    return d;
}

// ---------------------------------------------------------------------------
__global__ void k_pre(const float* __restrict__ rep) {
    int idx = blockIdx.x * blockDim.x + threadIdx.x;
    int c = idx >> 7;
    int k = idx & 127;
    g_repT[k * BBN + c] = rep[idx];
    if (idx < BBN) g_win[idx] = 0ULL;
}

// ---------------------------------------------------------------------------
__device__ __forceinline__ void row_update(const float* v, float& m, float& s) {
    float t = v[0];
#pragma unroll
    for (int j = 1; j < 8; ++j) t = fmaxf(t, v[j]);
#pragma unroll
    for (int o = 1; o < 32; o <<= 1)
        t = fmaxf(t, __shfl_xor_sync(0xffffffffu, t, o));
    float nm = fmaxf(m, t);
    float p = 0.0f;
#pragma unroll
    for (int j = 0; j < 8; ++j) p += __expf(v[j] - nm);
#pragma unroll
    for (int o = 1; o < 32; o <<= 1)
        p += __shfl_xor_sync(0xffffffffu, p, o);
    s = fmaf(s, __expf(m - nm), p);
    m = nm;
}

// ---------------------------------------------------------------------------
// Main fused kernel, one CTA per (t, 128-row block).
//   Phase 1: A[128x128] = E_t[rows,256] @ W_t[256,128]   (f32x2, h-pairs)
//   Phase 2: 8 column-tiles of 256: S = A @ rep^T, online softmax (f32x2, b-pairs)
// ---------------------------------------------------------------------------
__global__ void __launch_bounds__(256, 1)
k_main(const float* __restrict__ E, const float* __restrict__ W) {
    extern __shared__ float sm[];
    float* sAT   = sm;                      // [128][LDT]  A transposed [h][b]
    float* sX    = sm + 128 * LDT;          // phase1: sE+sW / phase2: sR
    float* sE    = sX;                      // [128][36]
    float* sW    = sX + 128 * 36;           // [32][LDT]
    float* sR    = sX;                      // [128][LDC2] repT tile [k][c]
    float* sDiag = sm + 128 * LDT + 128 * LDC2;  // [128]
    float* sRed  = sDiag + 128;             // [8]

    const int t      = blockIdx.y;
    const int rb     = blockIdx.x;
    const int base_b = rb * 128;
    const int tid    = threadIdx.x;

    const float* Et = E + (size_t)t * BBN * DD;
    const float* Wt = W + (size_t)t * DD * DHH;

    // ---------------- Phase 1: A = E @ W (h-pairs packed) ----------------
    {
        const int tx1 = tid & 15;          // h group: cols tx1*8 .. +8
        const int ty1 = tid >> 4;          // b group: rows ty1*8 .. +8

        u64 p1[8][4];
#pragma unroll
        for (int i = 0; i < 8; ++i)
#pragma unroll
            for (int jp = 0; jp < 4; ++jp) p1[i][jp] = 0ULL;

        for (int dk = 0; dk < DD; dk += 32) {
            __syncthreads();
            {   // E chunk [128 r x 32 k] -> sE[r][kk]
                int qk = tid & 7;
                int r0 = tid >> 3;
#pragma unroll
                for (int it = 0; it < 4; ++it) {
                    int r = r0 + it * 32;
                    float4 v = *(const float4*)(Et + (size_t)(base_b + r) * DD + dk + qk * 4);
                    *(float4*)(sE + r * 36 + qk * 4) = v;
                }
            }
            {   // W chunk [32 k x 128 h] -> sW[kk][h]
                int q   = tid & 31;
                int kk0 = tid >> 5;
#pragma unroll
                for (int it = 0; it < 4; ++it) {
                    int kk = kk0 + it * 8;
                    float4 v = *(const float4*)(Wt + (size_t)(dk + kk) * DHH + q * 4);
                    *(float4*)(sW + kk * LDT + q * 4) = v;
                }
            }
            __syncthreads();
#pragma unroll 2
            for (int kd = 0; kd < 32; ++kd) {
                u64 aa[8];
#pragma unroll
                for (int i = 0; i < 8; ++i)
                    aa[i] = pk2(sE[(ty1 * 8 + i) * 36 + kd]);
                ulonglong2 b01 = *(const ulonglong2*)(sW + kd * LDT + tx1 * 8);
                ulonglong2 b23 = *(const ulonglong2*)(sW + kd * LDT + tx1 * 8 + 4);
                u64 b2[4] = {b01.x, b01.y, b23.x, b23.y};
#pragma unroll
                for (int i = 0; i < 8; ++i)
#pragma unroll
                    for (int jp = 0; jp < 4; ++jp)
                        p1[i][jp] = ffma2(aa[i], b2[jp], p1[i][jp]);
            }
        }
        __syncthreads();

        // store A transposed into sAT[h][b]; rotate jp by tx1 to spread banks
#pragma unroll
        for (int i = 0; i < 8; ++i) {
#pragma unroll
            for (int jj = 0; jj < 4; ++jj) {
                int jp = (jj + tx1) & 3;
                float lo, hi; upk(p1[i][jp], lo, hi);
                int h0 = tx1 * 8 + 2 * jp;
                int b  = ty1 * 8 + i;
                sAT[h0 * LDT + b]       = lo;
                sAT[(h0 + 1) * LDT + b] = hi;
                if (t == TT - 1) {
                    g_A29T[(size_t)h0 * BBN + base_b + b]       = lo;
                    g_A29T[(size_t)(h0 + 1) * BBN + base_b + b] = hi;
                }
            }
        }
    }

    // ---------------- Phase 2: S = A @ rep^T, online softmax -------------
    const int ty = tid >> 5;   // warp id: rows ty*16 .. +16
    const int tx = tid & 31;   // cols tx*8 within 256-wide tile

    const float NEGINF = __int_as_float(0xff800000);
    float m[16], s[16];
#pragma unroll
    for (int r = 0; r < 16; ++r) { m[r] = NEGINF; s[r] = 0.0f; }

    for (int ct = 0; ct < 8; ++ct) {
        __syncthreads();
        {   // load rep tile [k 0..127][c ct*256 .. +256]
            int q  = tid & 63;
            int k0 = tid >> 6;
#pragma unroll
            for (int it = 0; it < 32; ++it) {
                int k = k0 + it * 4;
                *(float4*)(sR + k * LDC2 + q * 4) =
                    *(const float4*)(g_repT + (size_t)k * BBN + ct * 256 + q * 4);
            }
        }
        __syncthreads();

        u64 acc2[8][8];
#pragma unroll
        for (int ip = 0; ip < 8; ++ip)
#pragma unroll
            for (int j = 0; j < 8; ++j) acc2[ip][j] = 0ULL;

#pragma unroll 2
        for (int kd = 0; kd < 128; ++kd) {
            ulonglong2 a01 = *(const ulonglong2*)(sAT + kd * LDT + ty * 16);
            ulonglong2 a23 = *(const ulonglong2*)(sAT + kd * LDT + ty * 16 + 4);
            ulonglong2 a45 = *(const ulonglong2*)(sAT + kd * LDT + ty * 16 + 8);
            ulonglong2 a67 = *(const ulonglong2*)(sAT + kd * LDT + ty * 16 + 12);
            u64 a2[8] = {a01.x, a01.y, a23.x, a23.y, a45.x, a45.y, a67.x, a67.y};
            float4 bq0 = *(const float4*)(sR + kd * LDC2 + tx * 8);
            float4 bq1 = *(const float4*)(sR + kd * LDC2 + tx * 8 + 4);
            u64 bb[8];
            bb[0] = pk2(bq0.x); bb[1] = pk2(bq0.y);
            bb[2] = pk2(bq0.z); bb[3] = pk2(bq0.w);
            bb[4] = pk2(bq1.x); bb[5] = pk2(bq1.y);
            bb[6] = pk2(bq1.z); bb[7] = pk2(bq1.w);
#pragma unroll
            for (int ip = 0; ip < 8; ++ip)
#pragma unroll
                for (int j = 0; j < 8; ++j)
                    acc2[ip][j] = ffma2(a2[ip], bb[j], acc2[ip][j]);
        }

        // diagonal capture (column tile containing this row block)
        if (ct == (rb >> 1)) {
            int coff = (rb & 1) * 128;
#pragma unroll
            for (int ip = 0; ip < 8; ++ip)
#pragma unroll
                for (int j = 0; j < 8; ++j) {
                    float lo, hi; upk(acc2[ip][j], lo, hi);
                    int r0 = ty * 16 + 2 * ip;
                    int c  = tx * 8 + j;
                    if (c == coff + r0)     sDiag[r0]     = lo;
                    if (c == coff + r0 + 1) sDiag[r0 + 1] = hi;
                }
        }

        // online softmax update (16 rows per thread, warp-wide reduce)
#pragma unroll
        for (int ip = 0; ip < 8; ++ip) {
            float v0[8], v1[8];
#pragma unroll
            for (int j = 0; j < 8; ++j) upk(acc2[ip][j], v0[j], v1[j]);
            row_update(v0, m[2 * ip],     s[2 * ip]);
            row_update(v1, m[2 * ip + 1], s[2 * ip + 1]);
        }
    }
    __syncthreads();   // sDiag visibility

    if (tx == 0) {
        float part = 0.0f;
#pragma unroll
        for (int r = 0; r < 16; ++r) {
            float lse = m[r] + __logf(s[r]);
            part += sDiag[ty * 16 + r] - lse;
            if (t == TT - 1) g_lse29[base_b + ty * 16 + r] = lse;
        }
        sRed[ty] = part;
    }
    __syncthreads();
    if (tid == 0) {
        float tot = 0.0f;
        for (int r = 0; r < 8; ++r) tot += sRed[r];
        g_nce[t * 16 + rb] = tot;
    }
}

// ---------------------------------------------------------------------------
// Accuracy pass (t = 29): per column c, argmax over b of (S[b,c] - lse[b]).
// ---------------------------------------------------------------------------
__global__ void __launch_bounds__(256, 1)
k_acc() {
    extern __shared__ float sm[];
    float* sRc = sm;                 // [k][c] rep tile
    float* sAb = sm + 128 * LDT;     // [k][b] A29 tile

    const int cb  = blockIdx.x;
    const int bb  = blockIdx.y;
    const int tid = threadIdx.x;
    const int tx  = tid & 15;
    const int ty  = tid >> 4;

    {
        int q  = tid & 31;
        int k0 = tid >> 5;
#pragma unroll
        for (int it = 0; it < 16; ++it) {
            int k = k0 + it * 8;
            *(float4*)(sRc + k * LDT + q * 4) =
                *(const float4*)(g_repT + (size_t)k * BBN + cb * 128 + q * 4);
            *(float4*)(sAb + k * LDT + q * 4) =
                *(const float4*)(g_A29T + (size_t)k * BBN + bb * 128 + q * 4);
        }
    }
    __syncthreads();

    float acc[8][8];
#pragma unroll
    for (int i = 0; i < 8; ++i)
#pragma unroll
        for (int j = 0; j < 8; ++j) acc[i][j] = 0.0f;

#pragma unroll 4
    for (int kd = 0; kd < 128; ++kd) {
        float4 a0 = *(const float4*)(sRc + kd * LDT + ty * 8);
        float4 a1 = *(const float4*)(sRc + kd * LDT + ty * 8 + 4);
        float4 b0 = *(const float4*)(sAb + kd * LDT + tx * 8);
        float4 b1 = *(const float4*)(sAb + kd * LDT + tx * 8 + 4);
        float a[8] = {a0.x, a0.y, a0.z, a0.w, a1.x, a1.y, a1.z, a1.w};
        float b[8] = {b0.x, b0.y, b0.z, b0.w, b1.x, b1.y, b1.z, b1.w};
#pragma unroll
        for (int i = 0; i < 8; ++i)
#pragma unroll
            for (int j = 0; j < 8; ++j)
                acc[i][j] = fmaf(a[i], b[j], acc[i][j]);
    }

    float lse[8];
#pragma unroll
    for (int j = 0; j < 8; ++j) lse[j] = g_lse29[bb * 128 + tx * 8 + j];

#pragma unroll
    for (int i = 0; i < 8; ++i) {
        unsigned long long best = 0ULL;
#pragma unroll
        for (int j = 0; j < 8; ++j) {
            float v = acc[i][j] - lse[j];
            unsigned u = __float_as_uint(v);
            u = (u & 0x80000000u) ? ~u : (u | 0x80000000u);
            unsigned long long key =
                ((unsigned long long)u << 32) | (unsigned)(bb * 128 + tx * 8 + j);
            if (key > best) best = key;
        }
#pragma unroll
        for (int msk = 1; msk < 16; msk <<= 1) {
            unsigned long long o = __shfl_xor_sync(0xffffffffu, best, msk);
            if (o > best) best = o;
        }
        if (tx == 0)
            atomicMax(&g_win[cb * 128 + ty * 8 + i], best);
    }
}

// ---------------------------------------------------------------------------
__global__ void k_fin(float* __restrict__ out, int out_size) {
    __shared__ double rd[256];
    __shared__ int    ri[256];
    int tid = threadIdx.x;

    int cnt = 0;
    for (int c = tid; c < BBN; c += 256)
        cnt += ((unsigned)(g_win[c] & 0xffffffffULL) == (unsigned)c);

    double sum = 0.0;
    for (int i = tid; i < TT * 16; i += 256) sum += (double)g_nce[i];

    rd[tid] = sum; ri[tid] = cnt;
    __syncthreads();
    for (int st = 128; st > 0; st >>= 1) {
        if (tid < st) { rd[tid] += rd[tid + st]; ri[tid] += ri[tid + st]; }
        __syncthreads();
    }
    if (tid == 0) {
        out[0] = (float)ri[0] / (float)BBN;
        out[1] = (float)(rd[0] / (-(double)(BBN * TT)));
        out[2] = (float)BBN;
        out[3] = (float)(BBN * TT);
        for (int i = 4; i < out_size; ++i) out[i] = 0.0f;
    }
}

// ---------------------------------------------------------------------------
extern "C" void kernel_launch(void* const* d_in, const int* in_sizes, int n_in,
                              void* d_out, int out_size) {
    const float* E   = (const float*)d_in[0];   // [30, 2048, 256]
    const float* rep = (const float*)d_in[1];   // [2048, 128]
    const float* W   = (const float*)d_in[2];   // [30, 256, 128]
    // d_in[3] = Wk_b: row-constant shift, cancels in both softmaxes
    float* out = (float*)d_out;

    cudaFuncSetAttribute(k_main, cudaFuncAttributeMaxDynamicSharedMemorySize, SMEM_MAIN);
    cudaFuncSetAttribute(k_acc,  cudaFuncAttributeMaxDynamicSharedMemorySize, SMEM_ACC);

    k_pre<<<(BBN * DHH) / 256, 256>>>(rep);

    dim3 g2(16, TT);
    k_main<<<g2, 256, SMEM_MAIN>>>(E, W);

    dim3 g3(16, 16);
    k_acc<<<g3, 256, SMEM_ACC>>>();

    k_fin<<<1, 256>>>(out, out_size);
}

// round 4
// speedup vs baseline: 4.1505x; 3.8430x over previous
#include <cuda_runtime.h>
#include <cuda_bf16.h>
#include <math.h>
#include <cstdint>

#define TT  30
#define BBN 2048
#define DD  256
#define DHH 128

typedef unsigned long long u64;
typedef unsigned int       u32;
typedef unsigned short     u16;

// Feature gate: tcgen05 only exists on the 'a' (arch-specific) targets.
#if defined(__CUDA_ARCH_FEAT_SM103_ALL) || defined(__CUDA_ARCH_FEAT_SM100_ALL) || defined(__CUDA_ARCH_FEAT_SM101_ALL)
#define USE_TCGEN05 1
#else
#define USE_TCGEN05 0
#endif

// ---------------------------------------------------------------------------
// Device scratch (no allocation allowed)
// ---------------------------------------------------------------------------
__device__ float g_repT[DHH * BBN];        // rep transposed [k][c] (fp32)
__device__ float g_A29T[DHH * BBN];        // A(t=29) transposed [h][b]
__device__ float g_lse29[BBN];
__device__ float g_nce[TT * 16];
__device__ u64   g_win[BBN];
__device__ u16   g_repB[16 * 32768];       // per 128-col chunk: [hi 16K][lo 16K] u16, swizzled
__device__ u16   g_WB[TT * 2 * 32768];     // per (t, khalf): [hi][lo] of W^T tile, swizzled

// Unified dynamic smem size (max of tensor path 200704 and fallback 203296)
#define SMEM_UNI 203296
// Fallback layout strides
#define LDT  132
#define LDC2 264
#define SMEM_ACC ((2 * 128 * LDT) * 4)

// ---------------------------------------------------------------------------
// bf16 split helpers (used by pre-kernels on all targets)
// ---------------------------------------------------------------------------
__device__ __forceinline__ u16 f2bu(float f) {
    __nv_bfloat16 b = __float2bfloat16(f);
    return reinterpret_cast<u16&>(b);
}
__device__ __forceinline__ float b2f(u16 u) {
    __nv_bfloat16 b = reinterpret_cast<__nv_bfloat16&>(u);
    return __bfloat162float(b);
}
// blocked-atom swizzled u16 index for [m][k] tile (128x128 bf16, 8x64 atoms, SW128)
__device__ __forceinline__ int swz_idx(int m, int k) {
    int byte = (((m >> 3) + ((k >> 6) << 4)) << 10) + ((m & 7) << 7) + ((k & 63) << 1);
    byte ^= (byte >> 3) & 0x70;
    return byte >> 1;
}

// ---------------------------------------------------------------------------
// ffma2 helpers (fallback path)
// ---------------------------------------------------------------------------
__device__ __forceinline__ u64 pk2(float f) {
    u64 r; asm("mov.b64 %0, {%1, %1};" : "=l"(r) : "f"(f)); return r;
}
__device__ __forceinline__ void upk(u64 v, float& lo, float& hi) {
    asm("mov.b64 {%0, %1}, %2;" : "=f"(lo), "=f"(hi) : "l"(v));
}
__device__ __forceinline__ u64 ffma2(u64 a, u64 b, u64 c) {
    u64 d; asm("fma.rn.f32x2 %0, %1, %2, %3;" : "=l"(d) : "l"(a), "l"(b), "l"(c));
    return d;
}

// ---------------------------------------------------------------------------
// Pre-kernels (always run; produce both layouts)
// ---------------------------------------------------------------------------
__global__ void k_pre_rep(const float* __restrict__ rep) {
    int idx = blockIdx.x * blockDim.x + threadIdx.x;   // c*128 + k
    int c = idx >> 7, k = idx & 127;
    float v = rep[idx];
    g_repT[k * BBN + c] = v;
    u16 hi = f2bu(v);
    u16 lo = f2bu(v - b2f(hi));
    int cb = c >> 7, cl = c & 127;
    g_repB[cb * 32768 + swz_idx(cl, k)]         = hi;
    g_repB[cb * 32768 + 16384 + swz_idx(cl, k)] = lo;
    if (idx < BBN) g_win[idx] = 0ULL;
}

__global__ void k_pre_w(const float* __restrict__ W) {
    int idx = blockIdx.x * blockDim.x + threadIdx.x;   // t*DD*DHH + d*DHH + h
    int t = idx / (DD * DHH);
    int r = idx - t * DD * DHH;
    int d = r / DHH, h = r - d * DHH;
    float v = W[idx];
    u16 hi = f2bu(v);
    u16 lo = f2bu(v - b2f(hi));
    int half = d >> 7, kl = d & 127;
    int base = t * 65536 + half * 32768;
    g_WB[base + swz_idx(h, kl)]         = hi;
    g_WB[base + 16384 + swz_idx(h, kl)] = lo;
}

#if USE_TCGEN05
// ===========================================================================
// tcgen05 machinery (compiled ONLY on 'a' targets)
// ===========================================================================
__device__ __forceinline__ u32 elect_one_pred() {
    u32 pred;
    asm volatile("{\n\t.reg .pred p;\n\telect.sync _|p, 0xFFFFFFFF;\n\tselp.b32 %0, 1, 0, p;\n\t}" : "=r"(pred));
    return pred;
}
__device__ __forceinline__ u32 smem_to_u32(const void* p) {
    u32 a;
    asm("{ .reg .u64 t; cvta.to.shared.u64 t, %1; cvt.u32.u64 %0, t; }" : "=r"(a) : "l"(p));
    return a;
}
#define TCGEN05_ALLOC(sa, n) \
    asm volatile("tcgen05.alloc.cta_group::1.sync.aligned.shared::cta.b32 [%0], %1;" :: "r"((u32)(sa)), "r"((u32)(n)) : "memory")
#define TCGEN05_DEALLOC(ta, n) \
    asm volatile("tcgen05.dealloc.cta_group::1.sync.aligned.b32 %0, %1;" :: "r"(ta), "r"((u32)(n)))
#define TCGEN05_RELINQ() \
    asm volatile("tcgen05.relinquish_alloc_permit.cta_group::1.sync.aligned;")
#define TCGEN05_COMMIT(mb) \
    asm volatile("tcgen05.commit.cta_group::1.mbarrier::arrive::one.shared::cluster.b64 [%0];" :: "r"((u32)(mb)) : "memory")
#define TCGEN05_FENCE_BEFORE()  asm volatile("tcgen05.fence::before_thread_sync;" ::: "memory")
#define TCGEN05_FENCE_AFTER()   asm volatile("tcgen05.fence::after_thread_sync;" ::: "memory")
#define TCGEN05_WAIT_LD()       asm volatile("tcgen05.wait::ld.sync.aligned;" ::: "memory")
#define FENCE_PROXY()           asm volatile("fence.proxy.async.shared::cta;" ::: "memory")
#define MBARRIER_INIT(mb, cnt) \
    asm volatile("mbarrier.init.shared.b64 [%0], %1;" :: "r"((u32)(mb)), "r"((u32)(cnt)) : "memory")
#define MBARRIER_INVAL(mb) \
    asm volatile("mbarrier.inval.shared.b64 [%0];" :: "r"((u32)(mb)) : "memory")
#define MBARRIER_WAIT_PARITY(mb, ph) do {                                          \
    u32 _m = (u32)(mb); u32 _p = (u32)(ph); u32 _d;                                \
    asm volatile("{\n\t.reg .pred p;\n\t"                                          \
        "mbarrier.try_wait.parity.acquire.cta.shared::cta.b64 p, [%1], %2;\n\t"    \
        "selp.b32 %0, 1, 0, p;\n\t}" : "=r"(_d) : "r"(_m), "r"(_p) : "memory");    \
    if (!_d) {                                                                     \
        asm volatile("{\n\t.reg .pred P1;\n\t"                                     \
        "WL_%=:\n\t"                                                               \
        "mbarrier.try_wait.parity.acquire.cta.shared::cta.b64 P1, [%0], %1, 0x989680;\n\t" \
        "@P1 bra.uni WD_%=;\n\t"                                                   \
        "bra.uni WL_%=;\n\t"                                                       \
        "WD_%=:\n\t}" :: "r"(_m), "r"(_p) : "memory");                             \
    }                                                                              \
} while (0)

#define TCGEN05_LD_32X32B_X32(r, ta) \
    asm volatile( \
        "tcgen05.ld.sync.aligned.32x32b.x32.b32 " \
        "{%0, %1, %2, %3, %4, %5, %6, %7, " \
        " %8, %9, %10, %11, %12, %13, %14, %15, " \
        " %16, %17, %18, %19, %20, %21, %22, %23, " \
        " %24, %25, %26, %27, %28, %29, %30, %31}, [%32];" \
        : "=r"((r)[0]),  "=r"((r)[1]),  "=r"((r)[2]),  "=r"((r)[3]), \
          "=r"((r)[4]),  "=r"((r)[5]),  "=r"((r)[6]),  "=r"((r)[7]), \
          "=r"((r)[8]),  "=r"((r)[9]),  "=r"((r)[10]), "=r"((r)[11]), \
          "=r"((r)[12]), "=r"((r)[13]), "=r"((r)[14]), "=r"((r)[15]), \
          "=r"((r)[16]), "=r"((r)[17]), "=r"((r)[18]), "=r"((r)[19]), \
          "=r"((r)[20]), "=r"((r)[21]), "=r"((r)[22]), "=r"((r)[23]), \
          "=r"((r)[24]), "=r"((r)[25]), "=r"((r)[26]), "=r"((r)[27]), \
          "=r"((r)[28]), "=r"((r)[29]), "=r"((r)[30]), "=r"((r)[31]) \
        : "r"(ta))

__device__ __forceinline__ void mma_f16_ss(u32 d, u64 ad, u64 bd, u32 idesc, u32 en) {
    asm volatile(
        "{\n\t.reg .pred p;\n\tsetp.ne.u32 p, %5, 0;\n\t"
        "tcgen05.mma.cta_group::1.kind::f16 [%0], %1, %2, %3, {%4, %4, %4, %4}, p;\n\t}"
        :: "r"(d), "l"(ad), "l"(bd), "r"(idesc), "r"(0u), "r"(en) : "memory");
}

// SW128 K-major desc: LBO=1, SBO=64, layout=2, version=1
static constexpr u64 DESC_BASE =
    (u64(2) << 61) | (u64(1) << 46) | (u64(64) << 32) | (u64(1) << 16);
#define MK_DESC(a) (DESC_BASE | ((u64)((a) >> 4) & 0x3FFF))
// idesc: dtype F32, a/b BF16, N=128, M=128
#define IDESC 0x8200490u

// Tensor-path SMEM map (bytes)
#define SM_TMEMPTR 0
#define SM_MG      8
#define SM_FS0     16
#define SM_FS1     24
#define SM_DIAG    64
#define SM_MS      576
#define SM_RED     2624
#define SM_A2      4096
#define SM_B0      69632
#define SM_B1      135168

__device__ __forceinline__ void stage_E(const float* __restrict__ Et, int base_b, int dk,
                                        char* smc, int tid) {
    int row = tid >> 1;
    int cs  = (tid & 1) * 64;
    const float4* src = (const float4*)(Et + (size_t)(base_b + row) * DD + dk + cs);
    u16* hb = (u16*)(smc + SM_A2);
    u16* lb = hb + 16384;
#pragma unroll
    for (int q = 0; q < 16; ++q) {
        float4 v = src[q];
        int k = cs + q * 4;
        u16 h0 = f2bu(v.x), h1 = f2bu(v.y), h2 = f2bu(v.z), h3 = f2bu(v.w);
        u16 l0 = f2bu(v.x - b2f(h0)), l1 = f2bu(v.y - b2f(h1));
        u16 l2 = f2bu(v.z - b2f(h2)), l3 = f2bu(v.w - b2f(h3));
        uint2 hw = make_uint2((u32)h0 | ((u32)h1 << 16), (u32)h2 | ((u32)h3 << 16));
        uint2 lw = make_uint2((u32)l0 | ((u32)l1 << 16), (u32)l2 | ((u32)l3 << 16));
        int si = swz_idx(row, k);
        *(uint2*)(hb + si) = hw;
        *(uint2*)(lb + si) = lw;
    }
}

__device__ __forceinline__ void mma_pass8(u32 d, u64 ad, u64 bd, u32 en0) {
#pragma unroll
    for (int j = 0; j < 8; ++j) {
        u64 off = (u64)((j >> 2) * 1024 + (j & 3) * 2);
        mma_f16_ss(d, ad + off, bd + off, IDESC, j == 0 ? en0 : 1u);
    }
}
#endif  // USE_TCGEN05

// ---------------------------------------------------------------------------
// Fallback helper: online softmax row update (warp-wide over 32 lanes)
// ---------------------------------------------------------------------------
__device__ __forceinline__ void row_update(const float* v, float& m, float& s) {
    float t = v[0];
#pragma unroll
    for (int j = 1; j < 8; ++j) t = fmaxf(t, v[j]);
#pragma unroll
    for (int o = 1; o < 32; o <<= 1)
        t = fmaxf(t, __shfl_xor_sync(0xffffffffu, t, o));
    float nm = fmaxf(m, t);
    float p = 0.0f;
#pragma unroll
    for (int j = 0; j < 8; ++j) p += __expf(v[j] - nm);
#pragma unroll
    for (int o = 1; o < 32; o <<= 1)
        p += __shfl_xor_sync(0xffffffffu, p, o);
    s = fmaf(s, __expf(m - nm), p);
    m = nm;
}

// ---------------------------------------------------------------------------
// Main kernel: tensor body on 'a' targets, ffma2 body otherwise
// ---------------------------------------------------------------------------
__global__ void __launch_bounds__(256, 1)
k_main2(const float* __restrict__ E, const float* __restrict__ W) {
    extern __shared__ char smc[];
#if USE_TCGEN05
    const u32 sb = smem_to_u32(smc);
    float* sDiag = (float*)(smc + SM_DIAG);
    float* sMS   = (float*)(smc + SM_MS);
    float* sRed  = (float*)(smc + SM_RED);

    const int t      = blockIdx.y;
    const int rb     = blockIdx.x;
    const int base_b = rb * 128;
    const int tid    = threadIdx.x;
    const int wid    = tid >> 5;
    const int lane   = tid & 31;
    const int sub    = wid & 3;
    const int chalf  = wid >> 2;
    const int r_loc  = sub * 32 + lane;

    const float* Et = E + (size_t)t * BBN * DD;

    if (wid == 0) TCGEN05_ALLOC(sb + SM_TMEMPTR, 512);
    if (tid == 0) {
        MBARRIER_INIT(sb + SM_MG,  1);
        MBARRIER_INIT(sb + SM_FS0, 1);
        MBARRIER_INIT(sb + SM_FS1, 1);
    }
    __syncthreads();
    u32 tb;
    asm volatile("ld.shared.b32 %0, [%1];" : "=r"(tb) : "r"(sb + SM_TMEMPTR));

    // ---------------- GEMM1: A[128x128] = E_t @ W_t (bf16-split x3) -------
    {
        const float4* src = (const float4*)(g_WB + t * 65536);
        float4* dst = (float4*)(smc + SM_B0);
#pragma unroll
        for (int i = 0; i < 32; ++i) dst[tid + i * 256] = src[tid + i * 256];
    }
    stage_E(Et, base_b, 0, smc, tid);
    FENCE_PROXY();
    __syncthreads();

    const u64 aH = MK_DESC(sb + SM_A2);
    const u64 aL = MK_DESC(sb + SM_A2 + 32768);
    if (wid == 0 && elect_one_pred()) {
        u64 bH = MK_DESC(sb + SM_B0), bL = MK_DESC(sb + SM_B0 + 32768);
        mma_pass8(tb, aH, bH, 0u);
        mma_pass8(tb, aH, bL, 1u);
        mma_pass8(tb, aL, bH, 1u);
        TCGEN05_COMMIT(sb + SM_MG);
    }
    MBARRIER_WAIT_PARITY(sb + SM_MG, 0);

    stage_E(Et, base_b, 128, smc, tid);
    FENCE_PROXY();
    __syncthreads();
    if (wid == 0 && elect_one_pred()) {
        u64 bH = MK_DESC(sb + SM_B1), bL = MK_DESC(sb + SM_B1 + 32768);
        mma_pass8(tb, aH, bH, 1u);
        mma_pass8(tb, aH, bL, 1u);
        mma_pass8(tb, aL, bH, 1u);
        TCGEN05_COMMIT(sb + SM_MG);
    }
    MBARRIER_WAIT_PARITY(sb + SM_MG, 1);
    TCGEN05_FENCE_AFTER();

    // ---------------- A epilogue: TMEM -> bf16 hi/lo in SM_A2 -------------
    {
        u32 a0[32], a1[32];
        TCGEN05_LD_32X32B_X32(a0, tb + chalf * 64);
        TCGEN05_LD_32X32B_X32(a1, tb + chalf * 64 + 32);
        TCGEN05_WAIT_LD();
        u16* hb = (u16*)(smc + SM_A2);
        u16* lb = hb + 16384;
#pragma unroll
        for (int q = 0; q < 8; ++q) {
            int k0 = chalf * 64 + q * 4;
            float v0 = __uint_as_float(a0[4 * q]),     v1 = __uint_as_float(a0[4 * q + 1]);
            float v2 = __uint_as_float(a0[4 * q + 2]), v3 = __uint_as_float(a0[4 * q + 3]);
            u16 h0 = f2bu(v0), h1 = f2bu(v1), h2 = f2bu(v2), h3 = f2bu(v3);
            uint2 hw = make_uint2((u32)h0 | ((u32)h1 << 16), (u32)h2 | ((u32)h3 << 16));
            uint2 lw = make_uint2((u32)f2bu(v0 - b2f(h0)) | ((u32)f2bu(v1 - b2f(h1)) << 16),
                                  (u32)f2bu(v2 - b2f(h2)) | ((u32)f2bu(v3 - b2f(h3)) << 16));
            int si = swz_idx(r_loc, k0);
            *(uint2*)(hb + si) = hw;
            *(uint2*)(lb + si) = lw;

            int k1 = chalf * 64 + 32 + q * 4;
            float w0 = __uint_as_float(a1[4 * q]),     w1 = __uint_as_float(a1[4 * q + 1]);
            float w2 = __uint_as_float(a1[4 * q + 2]), w3 = __uint_as_float(a1[4 * q + 3]);
            u16 g0 = f2bu(w0), g1 = f2bu(w1), g2 = f2bu(w2), g3 = f2bu(w3);
            uint2 hw1 = make_uint2((u32)g0 | ((u32)g1 << 16), (u32)g2 | ((u32)g3 << 16));
            uint2 lw1 = make_uint2((u32)f2bu(w0 - b2f(g0)) | ((u32)f2bu(w1 - b2f(g1)) << 16),
                                   (u32)f2bu(w2 - b2f(g2)) | ((u32)f2bu(w3 - b2f(g3)) << 16));
            int sj = swz_idx(r_loc, k1);
            *(uint2*)(hb + sj) = hw1;
            *(uint2*)(lb + sj) = lw1;
        }
        if (t == TT - 1) {
#pragma unroll
            for (int j = 0; j < 32; ++j) {
                g_A29T[(size_t)(chalf * 64 + j) * BBN + base_b + r_loc]      = __uint_as_float(a0[j]);
                g_A29T[(size_t)(chalf * 64 + 32 + j) * BBN + base_b + r_loc] = __uint_as_float(a1[j]);
            }
        }
        TCGEN05_FENCE_BEFORE();
        FENCE_PROXY();
    }

    // ---------------- GEMM2: 16 chunks of 128 cols, pipelined -------------
    {
        const float4* src = (const float4*)(g_repB);
        float4* dst = (float4*)(smc + SM_B0);
#pragma unroll
        for (int i = 0; i < 16; ++i) dst[tid + i * 256] = src[tid + i * 256];
    }
    FENCE_PROXY();
    __syncthreads();
    if (wid == 0 && elect_one_pred()) {
        u64 bH = MK_DESC(sb + SM_B0), bL = MK_DESC(sb + SM_B0 + 32768);
        mma_pass8(tb + 128, aH, bH, 0u);
        mma_pass8(tb + 128, aH, bL, 1u);
        mma_pass8(tb + 128, aL, bH, 1u);
        TCGEN05_COMMIT(sb + SM_FS0);
    }

    const float NEGINF = __int_as_float(0xff800000);
    float m = NEGINF, s = 0.0f;

    for (int i = 0; i < 16; ++i) {
        int p = i & 1;
        if (i < 15) {
            const float4* src = (const float4*)(g_repB + (i + 1) * 32768);
            float4* dst = (float4*)(smc + (p ? SM_B0 : SM_B1));
#pragma unroll
            for (int q = 0; q < 16; ++q) dst[tid + q * 256] = src[tid + q * 256];
            FENCE_PROXY();
        }
        MBARRIER_WAIT_PARITY(sb + (p ? SM_FS1 : SM_FS0), (i >> 1) & 1);
        TCGEN05_FENCE_AFTER();
        __syncthreads();
        if (i < 15 && wid == 0 && elect_one_pred()) {
            u32 boff = p ? SM_B0 : SM_B1;
            u64 bH = MK_DESC(sb + boff), bL = MK_DESC(sb + boff + 32768);
            u32 ddst = tb + 128 + 128 * (p ^ 1);
            mma_pass8(ddst, aH, bH, 0u);
            mma_pass8(ddst, aH, bL, 1u);
            mma_pass8(ddst, aL, bH, 1u);
            TCGEN05_COMMIT(sb + (p ? SM_FS0 : SM_FS1));
        }

        u32 v0[32], v1[32];
        TCGEN05_LD_32X32B_X32(v0, tb + 128 + 128 * p + chalf * 64);
        TCGEN05_LD_32X32B_X32(v1, tb + 128 + 128 * p + chalf * 64 + 32);
        TCGEN05_WAIT_LD();

        if (i == rb) {
            int jd = r_loc - chalf * 64;
#pragma unroll
            for (int j = 0; j < 32; ++j) {
                if (j == jd)      sDiag[r_loc] = __uint_as_float(v0[j]);
                if (j + 32 == jd) sDiag[r_loc] = __uint_as_float(v1[j]);
            }
        }

        float lm = NEGINF;
#pragma unroll
        for (int j = 0; j < 32; ++j) {
            lm = fmaxf(lm, __uint_as_float(v0[j]));
            lm = fmaxf(lm, __uint_as_float(v1[j]));
        }
        float nm = fmaxf(m, lm);
        float add = 0.0f;
#pragma unroll
        for (int j = 0; j < 32; ++j) {
            add += __expf(__uint_as_float(v0[j]) - nm);
            add += __expf(__uint_as_float(v1[j]) - nm);
        }
        s = fmaf(s, __expf(m - nm), add);
        m = nm;
        TCGEN05_FENCE_BEFORE();
    }
    __syncthreads();

    sMS[r_loc * 4 + chalf * 2]     = m;
    sMS[r_loc * 4 + chalf * 2 + 1] = s;
    __syncthreads();

    if (tid < 128) {
        float m0 = sMS[tid * 4], s0 = sMS[tid * 4 + 1];
        float m1 = sMS[tid * 4 + 2], s1 = sMS[tid * 4 + 3];
        float mm = fmaxf(m0, m1);
        float ss = s0 * __expf(m0 - mm) + s1 * __expf(m1 - mm);
        float lse = mm + __logf(ss);
        if (t == TT - 1) g_lse29[base_b + tid] = lse;
        float part = sDiag[tid] - lse;
#pragma unroll
        for (int o = 1; o < 32; o <<= 1)
            part += __shfl_xor_sync(0xffffffffu, part, o);
        if ((tid & 31) == 0) sRed[tid >> 5] = part;
    }
    __syncthreads();
    if (tid == 0)
        g_nce[t * 16 + rb] = sRed[0] + sRed[1] + sRed[2] + sRed[3];

    if (tid == 0) {
        MBARRIER_INVAL(sb + SM_MG);
        MBARRIER_INVAL(sb + SM_FS0);
        MBARRIER_INVAL(sb + SM_FS1);
    }
    __syncthreads();
    if (wid == 0) {
        TCGEN05_RELINQ();
        TCGEN05_DEALLOC(tb, 512);
    }

#else  // ================= fallback: ffma2 body (R2, 891us) =================
    float* sm    = (float*)smc;
    float* sAT   = sm;                      // [128][LDT]
    float* sX    = sm + 128 * LDT;
    float* sE    = sX;                      // [128][36]
    float* sW    = sX + 128 * 36;           // [32][LDT]
    float* sR    = sX;                      // [128][LDC2]
    float* sDiag = sm + 128 * LDT + 128 * LDC2;
    float* sRed  = sDiag + 128;

    const int t      = blockIdx.y;
    const int rb     = blockIdx.x;
    const int base_b = rb * 128;
    const int tid    = threadIdx.x;

    const float* Et = E + (size_t)t * BBN * DD;
    const float* Wt = W + (size_t)t * DD * DHH;

    {
        const int tx1 = tid & 15;
        const int ty1 = tid >> 4;

        u64 p1[8][4];
#pragma unroll
        for (int i = 0; i < 8; ++i)
#pragma unroll
            for (int jp = 0; jp < 4; ++jp) p1[i][jp] = 0ULL;

        for (int dk = 0; dk < DD; dk += 32) {
            __syncthreads();
            {
                int qk = tid & 7;
                int r0 = tid >> 3;
#pragma unroll
                for (int it = 0; it < 4; ++it) {
                    int r = r0 + it * 32;
                    float4 v = *(const float4*)(Et + (size_t)(base_b + r) * DD + dk + qk * 4);
                    *(float4*)(sE + r * 36 + qk * 4) = v;
                }
            }
            {
                int q   = tid & 31;
                int kk0 = tid >> 5;
#pragma unroll
                for (int it = 0; it < 4; ++it) {
                    int kk = kk0 + it * 8;
                    float4 v = *(const float4*)(Wt + (size_t)(dk + kk) * DHH + q * 4);
                    *(float4*)(sW + kk * LDT + q * 4) = v;
                }
            }
            __syncthreads();
#pragma unroll 2
            for (int kd = 0; kd < 32; ++kd) {
                u64 aa[8];
#pragma unroll
                for (int i = 0; i < 8; ++i)
                    aa[i] = pk2(sE[(ty1 * 8 + i) * 36 + kd]);
                ulonglong2 b01 = *(const ulonglong2*)(sW + kd * LDT + tx1 * 8);
                ulonglong2 b23 = *(const ulonglong2*)(sW + kd * LDT + tx1 * 8 + 4);
                u64 b2[4] = {b01.x, b01.y, b23.x, b23.y};
#pragma unroll
                for (int i = 0; i < 8; ++i)
#pragma unroll
                    for (int jp = 0; jp < 4; ++jp)
                        p1[i][jp] = ffma2(aa[i], b2[jp], p1[i][jp]);
            }
        }
        __syncthreads();

#pragma unroll
        for (int i = 0; i < 8; ++i) {
#pragma unroll
            for (int jj = 0; jj < 4; ++jj) {
                int jp = (jj + tx1) & 3;
                float lo, hi; upk(p1[i][jp], lo, hi);
                int h0 = tx1 * 8 + 2 * jp;
                int b  = ty1 * 8 + i;
                sAT[h0 * LDT + b]       = lo;
                sAT[(h0 + 1) * LDT + b] = hi;
                if (t == TT - 1) {
                    g_A29T[(size_t)h0 * BBN + base_b + b]       = lo;
                    g_A29T[(size_t)(h0 + 1) * BBN + base_b + b] = hi;
                }
            }
        }
    }

    const int ty = tid >> 5;
    const int tx = tid & 31;

    const float NEGINF = __int_as_float(0xff800000);
    float m[16], s[16];
#pragma unroll
    for (int r = 0; r < 16; ++r) { m[r] = NEGINF; s[r] = 0.0f; }

    for (int ct = 0; ct < 8; ++ct) {
        __syncthreads();
        {
            int q  = tid & 63;
            int k0 = tid >> 6;
#pragma unroll
            for (int it = 0; it < 32; ++it) {
                int k = k0 + it * 4;
                *(float4*)(sR + k * LDC2 + q * 4) =
                    *(const float4*)(g_repT + (size_t)k * BBN + ct * 256 + q * 4);
            }
        }
        __syncthreads();

        u64 acc2[8][8];
#pragma unroll
        for (int ip = 0; ip < 8; ++ip)
#pragma unroll
            for (int j = 0; j < 8; ++j) acc2[ip][j] = 0ULL;

#pragma unroll 2
        for (int kd = 0; kd < 128; ++kd) {
            ulonglong2 a01 = *(const ulonglong2*)(sAT + kd * LDT + ty * 16);
            ulonglong2 a23 = *(const ulonglong2*)(sAT + kd * LDT + ty * 16 + 4);
            ulonglong2 a45 = *(const ulonglong2*)(sAT + kd * LDT + ty * 16 + 8);
            ulonglong2 a67 = *(const ulonglong2*)(sAT + kd * LDT + ty * 16 + 12);
            u64 a2[8] = {a01.x, a01.y, a23.x, a23.y, a45.x, a45.y, a67.x, a67.y};
            float4 bq0 = *(const float4*)(sR + kd * LDC2 + tx * 8);
            float4 bq1 = *(const float4*)(sR + kd * LDC2 + tx * 8 + 4);
            u64 bb[8];
            bb[0] = pk2(bq0.x); bb[1] = pk2(bq0.y);
            bb[2] = pk2(bq0.z); bb[3] = pk2(bq0.w);
            bb[4] = pk2(bq1.x); bb[5] = pk2(bq1.y);
            bb[6] = pk2(bq1.z); bb[7] = pk2(bq1.w);
#pragma unroll
            for (int ip = 0; ip < 8; ++ip)
#pragma unroll
                for (int j = 0; j < 8; ++j)
                    acc2[ip][j] = ffma2(a2[ip], bb[j], acc2[ip][j]);
        }

        if (ct == (rb >> 1)) {
            int coff = (rb & 1) * 128;
#pragma unroll
            for (int ip = 0; ip < 8; ++ip)
#pragma unroll
                for (int j = 0; j < 8; ++j) {
                    float lo, hi; upk(acc2[ip][j], lo, hi);
                    int r0 = ty * 16 + 2 * ip;
                    int c  = tx * 8 + j;
                    if (c == coff + r0)     sDiag[r0]     = lo;
                    if (c == coff + r0 + 1) sDiag[r0 + 1] = hi;
                }
        }

#pragma unroll
        for (int ip = 0; ip < 8; ++ip) {
            float v0[8], v1[8];
#pragma unroll
            for (int j = 0; j < 8; ++j) upk(acc2[ip][j], v0[j], v1[j]);
            row_update(v0, m[2 * ip],     s[2 * ip]);
            row_update(v1, m[2 * ip + 1], s[2 * ip + 1]);
        }
    }
    __syncthreads();

    if (tx == 0) {
        float part = 0.0f;
#pragma unroll
        for (int r = 0; r < 16; ++r) {
            float lse = m[r] + __logf(s[r]);
            part += sDiag[ty * 16 + r] - lse;
            if (t == TT - 1) g_lse29[base_b + ty * 16 + r] = lse;
        }
        sRed[ty] = part;
    }
    __syncthreads();
    if (tid == 0) {
        float tot = 0.0f;
        for (int r = 0; r < 8; ++r) tot += sRed[r];
        g_nce[t * 16 + rb] = tot;
    }
#endif
}

// ---------------------------------------------------------------------------
// Accuracy pass (t=29), fp32
// ---------------------------------------------------------------------------
__global__ void __launch_bounds__(256, 1)
k_acc() {
    extern __shared__ float sm[];
    float* sRc = sm;
    float* sAb = sm + 128 * LDT;

    const int cb  = blockIdx.x;
    const int bb  = blockIdx.y;
    const int tid = threadIdx.x;
    const int tx  = tid & 15;
    const int ty  = tid >> 4;

    {
        int q  = tid & 31;
        int k0 = tid >> 5;
#pragma unroll
        for (int it = 0; it < 16; ++it) {
            int k = k0 + it * 8;
            *(float4*)(sRc + k * LDT + q * 4) =
                *(const float4*)(g_repT + (size_t)k * BBN + cb * 128 + q * 4);
            *(float4*)(sAb + k * LDT + q * 4) =
                *(const float4*)(g_A29T + (size_t)k * BBN + bb * 128 + q * 4);
        }
    }
    __syncthreads();

    float acc[8][8];
#pragma unroll
    for (int i = 0; i < 8; ++i)
#pragma unroll
        for (int j = 0; j < 8; ++j) acc[i][j] = 0.0f;

#pragma unroll 4
    for (int kd = 0; kd < 128; ++kd) {
        float4 a0 = *(const float4*)(sRc + kd * LDT + ty * 8);
        float4 a1 = *(const float4*)(sRc + kd * LDT + ty * 8 + 4);
        float4 b0 = *(const float4*)(sAb + kd * LDT + tx * 8);
        float4 b1 = *(const float4*)(sAb + kd * LDT + tx * 8 + 4);
        float a[8] = {a0.x, a0.y, a0.z, a0.w, a1.x, a1.y, a1.z, a1.w};
        float b[8] = {b0.x, b0.y, b0.z, b0.w, b1.x, b1.y, b1.z, b1.w};
#pragma unroll
        for (int i = 0; i < 8; ++i)
#pragma unroll
            for (int j = 0; j < 8; ++j)
                acc[i][j] = fmaf(a[i], b[j], acc[i][j]);
    }

    float lse[8];
#pragma unroll
    for (int j = 0; j < 8; ++j) lse[j] = g_lse29[bb * 128 + tx * 8 + j];

#pragma unroll
    for (int i = 0; i < 8; ++i) {
        u64 best = 0ULL;
#pragma unroll
        for (int j = 0; j < 8; ++j) {
            float v = acc[i][j] - lse[j];
            u32 u = __float_as_uint(v);
            u = (u & 0x80000000u) ? ~u : (u | 0x80000000u);
            u64 key = ((u64)u << 32) | (u32)(bb * 128 + tx * 8 + j);
            if (key > best) best = key;
        }
#pragma unroll
        for (int msk = 1; msk < 16; msk <<= 1) {
            u64 o = __shfl_xor_sync(0xffffffffu, best, msk);
            if (o > best) best = o;
        }
        if (tx == 0)
            atomicMax(&g_win[cb * 128 + ty * 8 + i], best);
    }
}

// ---------------------------------------------------------------------------
__global__ void k_fin(float* __restrict__ out, int out_size) {
    __shared__ double rd[256];
    __shared__ int    ri[256];
    int tid = threadIdx.x;

    int cnt = 0;
    for (int c = tid; c < BBN; c += 256)
        cnt += ((u32)(g_win[c] & 0xffffffffULL) == (u32)c);

    double sum = 0.0;
    for (int i = tid; i < TT * 16; i += 256) sum += (double)g_nce[i];

    rd[tid] = sum; ri[tid] = cnt;
    __syncthreads();
    for (int st = 128; st > 0; st >>= 1) {
        if (tid < st) { rd[tid] += rd[tid + st]; ri[tid] += ri[tid + st]; }
        __syncthreads();
    }
    if (tid == 0) {
        out[0] = (float)ri[0] / (float)BBN;
        out[1] = (float)(rd[0] / (-(double)(BBN * TT)));
        out[2] = (float)BBN;
        out[3] = (float)(BBN * TT);
        for (int i = 4; i < out_size; ++i) out[i] = 0.0f;
    }
}

// ---------------------------------------------------------------------------
extern "C" void kernel_launch(void* const* d_in, const int* in_sizes, int n_in,
                              void* d_out, int out_size) {
    const float* E   = (const float*)d_in[0];   // [30, 2048, 256]
    const float* rep = (const float*)d_in[1];   // [2048, 128]
    const float* W   = (const float*)d_in[2];   // [30, 256, 128]
    // d_in[3] = Wk_b: row-constant shift, cancels in both softmaxes
    float* out = (float*)d_out;

    cudaFuncSetAttribute(k_main2, cudaFuncAttributeMaxDynamicSharedMemorySize, SMEM_UNI);
    cudaFuncSetAttribute(k_acc,   cudaFuncAttributeMaxDynamicSharedMemorySize, SMEM_ACC);

    k_pre_rep<<<(BBN * DHH) / 256, 256>>>(rep);
    k_pre_w<<<(TT * DD * DHH) / 256, 256>>>(W);

    dim3 g2(16, TT);
    k_main2<<<g2, 256, SMEM_UNI>>>(E, W);

    dim3 g3(16, 16);
    k_acc<<<g3, 256, SMEM_ACC>>>();

    k_fin<<<1, 256>>>(out, out_size);
}

// round 5
// speedup vs baseline: 4.5781x; 1.1030x over previous
#include <cuda_runtime.h>
#include <cuda_bf16.h>
#include <math.h>
#include <cstdint>

#define TT  30
#define BBN 2048
#define DD  256
#define DHH 128

typedef unsigned long long u64;
typedef unsigned int       u32;
typedef unsigned short     u16;

// Feature gate: tcgen05 only exists on the 'a' targets.
#if defined(__CUDA_ARCH_FEAT_SM103_ALL) || defined(__CUDA_ARCH_FEAT_SM100_ALL) || defined(__CUDA_ARCH_FEAT_SM101_ALL)
#define USE_TCGEN05 1
#else
#define USE_TCGEN05 0
#endif

// ---------------------------------------------------------------------------
// Device scratch
// ---------------------------------------------------------------------------
__device__ float g_A29T[DHH * BBN];        // A(t=29) transposed [h][b] fp32 (kept for debug)
__device__ float g_lse29[BBN];
__device__ float g_nce[TT * 16];
__device__ u64   g_win[BBN];
__device__ int   g_done = 0;
__device__ u16   g_repB[16 * 32768];       // per 128-col chunk: [hi 16K][lo 16K] u16, swizzled
__device__ u16   g_WB[TT * 2 * 32768];     // per (t, khalf): [hi][lo] of W^T tile, swizzled
__device__ u16   g_A29B[16 * 32768];       // per 128-row block: [hi][lo] of A29, swizzled

// ---------------------------------------------------------------------------
// bf16 helpers
// ---------------------------------------------------------------------------
__device__ __forceinline__ u16 f2bu(float f) {
    __nv_bfloat16 b = __float2bfloat16(f);
    return reinterpret_cast<u16&>(b);
}
__device__ __forceinline__ float b2f(u16 u) {
    __nv_bfloat16 b = reinterpret_cast<__nv_bfloat16&>(u);
    return __bfloat162float(b);
}
// blocked-atom swizzled u16 index for [m][k] tile (128x128 bf16, 8x64 atoms, SW128)
__device__ __forceinline__ int swz_idx(int m, int k) {
    int byte = (((m >> 3) + ((k >> 6) << 4)) << 10) + ((m & 7) << 7) + ((k & 63) << 1);
    byte ^= (byte >> 3) & 0x70;
    return byte >> 1;
}

// ---------------------------------------------------------------------------
// Pre-kernels
// ---------------------------------------------------------------------------
__global__ void k_pre_rep(const float* __restrict__ rep) {
    int idx = blockIdx.x * blockDim.x + threadIdx.x;   // c*128 + k
    int c = idx >> 7, k = idx & 127;
    float v = rep[idx];
    u16 hi = f2bu(v);
    u16 lo = f2bu(v - b2f(hi));
    int cb = c >> 7, cl = c & 127;
    g_repB[cb * 32768 + swz_idx(cl, k)]         = hi;
    g_repB[cb * 32768 + 16384 + swz_idx(cl, k)] = lo;
    if (idx < BBN) g_win[idx] = 0ULL;
}

__global__ void k_pre_w(const float* __restrict__ W) {
    int idx = blockIdx.x * blockDim.x + threadIdx.x;   // t*DD*DHH + d*DHH + h
    int t = idx / (DD * DHH);
    int r = idx - t * DD * DHH;
    int d = r / DHH, h = r - d * DHH;
    float v = W[idx];
    u16 hi = f2bu(v);
    u16 lo = f2bu(v - b2f(hi));
    int half = d >> 7, kl = d & 127;
    int base = t * 65536 + half * 32768;
    g_WB[base + swz_idx(h, kl)]         = hi;
    g_WB[base + 16384 + swz_idx(h, kl)] = lo;
}

#if USE_TCGEN05
// ===========================================================================
// tcgen05 machinery ('a' targets only)
// ===========================================================================
__device__ __forceinline__ u32 elect_one_pred() {
    u32 pred;
    asm volatile("{\n\t.reg .pred p;\n\telect.sync _|p, 0xFFFFFFFF;\n\tselp.b32 %0, 1, 0, p;\n\t}" : "=r"(pred));
    return pred;
}
__device__ __forceinline__ u32 smem_to_u32(const void* p) {
    u32 a;
    asm("{ .reg .u64 t; cvta.to.shared.u64 t, %1; cvt.u32.u64 %0, t; }" : "=r"(a) : "l"(p));
    return a;
}
#define TCGEN05_ALLOC(sa, n) \
    asm volatile("tcgen05.alloc.cta_group::1.sync.aligned.shared::cta.b32 [%0], %1;" :: "r"((u32)(sa)), "r"((u32)(n)) : "memory")
#define TCGEN05_DEALLOC(ta, n) \
    asm volatile("tcgen05.dealloc.cta_group::1.sync.aligned.b32 %0, %1;" :: "r"(ta), "r"((u32)(n)))
#define TCGEN05_RELINQ() \
    asm volatile("tcgen05.relinquish_alloc_permit.cta_group::1.sync.aligned;")
#define TCGEN05_COMMIT(mb) \
    asm volatile("tcgen05.commit.cta_group::1.mbarrier::arrive::one.shared::cluster.b64 [%0];" :: "r"((u32)(mb)) : "memory")
#define TCGEN05_FENCE_BEFORE()  asm volatile("tcgen05.fence::before_thread_sync;" ::: "memory")
#define TCGEN05_FENCE_AFTER()   asm volatile("tcgen05.fence::after_thread_sync;" ::: "memory")
#define TCGEN05_WAIT_LD()       asm volatile("tcgen05.wait::ld.sync.aligned;" ::: "memory")
#define FENCE_PROXY()           asm volatile("fence.proxy.async.shared::cta;" ::: "memory")
#define MBARRIER_INIT(mb, cnt) \
    asm volatile("mbarrier.init.shared.b64 [%0], %1;" :: "r"((u32)(mb)), "r"((u32)(cnt)) : "memory")
#define MBARRIER_INVAL(mb) \
    asm volatile("mbarrier.inval.shared.b64 [%0];" :: "r"((u32)(mb)) : "memory")
#define MBARRIER_WAIT_PARITY(mb, ph) do {                                          \
    u32 _m = (u32)(mb); u32 _p = (u32)(ph); u32 _d;                                \
    asm volatile("{\n\t.reg .pred p;\n\t"                                          \
        "mbarrier.try_wait.parity.acquire.cta.shared::cta.b64 p, [%1], %2;\n\t"    \
        "selp.b32 %0, 1, 0, p;\n\t}" : "=r"(_d) : "r"(_m), "r"(_p) : "memory");    \
    if (!_d) {                                                                     \
        asm volatile("{\n\t.reg .pred P1;\n\t"                                     \
        "WL_%=:\n\t"                                                               \
        "mbarrier.try_wait.parity.acquire.cta.shared::cta.b64 P1, [%0], %1, 0x989680;\n\t" \
        "@P1 bra.uni WD_%=;\n\t"                                                   \
        "bra.uni WL_%=;\n\t"                                                       \
        "WD_%=:\n\t}" :: "r"(_m), "r"(_p) : "memory");                             \
    }                                                                              \
} while (0)

#define TCGEN05_LD_32X32B_X32(r, ta) \
    asm volatile( \
        "tcgen05.ld.sync.aligned.32x32b.x32.b32 " \
        "{%0, %1, %2, %3, %4, %5, %6, %7, " \
        " %8, %9, %10, %11, %12, %13, %14, %15, " \
        " %16, %17, %18, %19, %20, %21, %22, %23, " \
        " %24, %25, %26, %27, %28, %29, %30, %31}, [%32];" \
        : "=r"((r)[0]),  "=r"((r)[1]),  "=r"((r)[2]),  "=r"((r)[3]), \
          "=r"((r)[4]),  "=r"((r)[5]),  "=r"((r)[6]),  "=r"((r)[7]), \
          "=r"((r)[8]),  "=r"((r)[9]),  "=r"((r)[10]), "=r"((r)[11]), \
          "=r"((r)[12]), "=r"((r)[13]), "=r"((r)[14]), "=r"((r)[15]), \
          "=r"((r)[16]), "=r"((r)[17]), "=r"((r)[18]), "=r"((r)[19]), \
          "=r"((r)[20]), "=r"((r)[21]), "=r"((r)[22]), "=r"((r)[23]), \
          "=r"((r)[24]), "=r"((r)[25]), "=r"((r)[26]), "=r"((r)[27]), \
          "=r"((r)[28]), "=r"((r)[29]), "=r"((r)[30]), "=r"((r)[31]) \
        : "r"(ta))

__device__ __forceinline__ void mma_f16_ss(u32 d, u64 ad, u64 bd, u32 idesc, u32 en) {
    asm volatile(
        "{\n\t.reg .pred p;\n\tsetp.ne.u32 p, %5, 0;\n\t"
        "tcgen05.mma.cta_group::1.kind::f16 [%0], %1, %2, %3, {%4, %4, %4, %4}, p;\n\t}"
        :: "r"(d), "l"(ad), "l"(bd), "r"(idesc), "r"(0u), "r"(en) : "memory");
}

static constexpr u64 DESC_BASE =
    (u64(2) << 61) | (u64(1) << 46) | (u64(64) << 32) | (u64(1) << 16);
#define MK_DESC(a) (DESC_BASE | ((u64)((a) >> 4) & 0x3FFF))
#define IDESC 0x8200490u     // F32 accum, BF16xBF16, M=128, N=128

__device__ __forceinline__ void mma_pass8(u32 d, u64 ad, u64 bd, u32 en0) {
#pragma unroll
    for (int j = 0; j < 8; ++j) {
        u64 off = (u64)((j >> 2) * 1024 + (j & 3) * 2);
        mma_f16_ss(d, ad + off, bd + off, IDESC, j == 0 ? en0 : 1u);
    }
}
#endif  // USE_TCGEN05

// ---------------------------------------------------------------------------
// SMEM maps (bytes)
// ---------------------------------------------------------------------------
#define SM_TMEMPTR 0
#define SM_MG      8
#define SM_FS0     16
#define SM_FS1     24
#define SM_DIAG    64        // 128 f32
#define SM_MS      576       // 512 f32? (uses 2048B)
#define SM_RED     2624
#define SM_R1      4096      // 32KB: E-hi stage / A-hi
#define SM_R2      36864     // 32KB
#define SM_R3      69632     // 32KB
#define SMEM_MAIN  102400

// k_acc2 smem
#define SA_TMEMPTR 0
#define SA_MB      8
#define SA_LAST    16
#define SA_LSE     64        // 128 f32
#define SA_RH      1024
#define SA_RL      33792
#define SA_AH      66560
#define SA_AL      99328
#define SMEM_ACC2  132096

#if USE_TCGEN05
__device__ __forceinline__ void copy32k(char* dst, const void* src, int tid) {
    const float4* s = (const float4*)src;
    float4* d = (float4*)dst;
#pragma unroll
    for (int i = 0; i < 8; ++i) d[tid + i * 256] = s[tid + i * 256];
}

// Stage E hi-only, swizzled: tile [128 rows][128 k] from Et + khalf*128
__device__ __forceinline__ void stage_E(const float* __restrict__ Et, int base_b, int dk,
                                        char* smc, int tid) {
    int row = tid >> 1;
    int cs  = (tid & 1) * 64;
    const float4* src = (const float4*)(Et + (size_t)(base_b + row) * DD + dk + cs);
    u16* hb = (u16*)(smc + SM_R1);
#pragma unroll
    for (int q = 0; q < 16; ++q) {
        float4 v = src[q];
        int k = cs + q * 4;
        uint2 hw = make_uint2((u32)f2bu(v.x) | ((u32)f2bu(v.y) << 16),
                              (u32)f2bu(v.z) | ((u32)f2bu(v.w) << 16));
        *(uint2*)(hb + swz_idx(row, k)) = hw;
    }
}
#endif

// ---------------------------------------------------------------------------
// Main fused kernel: per (t, 128-row block)
// ---------------------------------------------------------------------------
__global__ void __launch_bounds__(256, 2)
k_main2(const float* __restrict__ E) {
    extern __shared__ char smc[];
#if USE_TCGEN05
    const u32 sb = smem_to_u32(smc);
    float* sDiag = (float*)(smc + SM_DIAG);
    float* sMS   = (float*)(smc + SM_MS);
    float* sRed  = (float*)(smc + SM_RED);

    const int t      = blockIdx.y;
    const int rb     = blockIdx.x;
    const int base_b = rb * 128;
    const int tid    = threadIdx.x;
    const int wid    = tid >> 5;
    const int lane   = tid & 31;
    const int sub    = wid & 3;
    const int chalf  = wid >> 2;
    const int r_loc  = sub * 32 + lane;

    const float* Et = E + (size_t)t * BBN * DD;

    if (wid == 0) TCGEN05_ALLOC(sb + SM_TMEMPTR, 256);
    if (tid == 0) {
        MBARRIER_INIT(sb + SM_MG,  1);
        MBARRIER_INIT(sb + SM_FS0, 1);
        MBARRIER_INIT(sb + SM_FS1, 1);
    }
    __syncthreads();
    u32 tb;
    asm volatile("ld.shared.b32 %0, [%1];" : "=r"(tb) : "r"(sb + SM_TMEMPTR));

    const u64 dR1 = MK_DESC(sb + SM_R1);
    const u64 dR2 = MK_DESC(sb + SM_R2);
    const u64 dR3 = MK_DESC(sb + SM_R3);

    // ------------- GEMM1 (2-pass): A = Eh·Wh + Eh·Wl, two K-halves --------
#pragma unroll
    for (int kh = 0; kh < 2; ++kh) {
        if (kh == 1) MBARRIER_WAIT_PARITY(sb + SM_MG, 0);   // khalf0 MMAs done
        copy32k(smc + SM_R2, g_WB + t * 65536 + kh * 32768, tid);          // W hi
        copy32k(smc + SM_R3, g_WB + t * 65536 + kh * 32768 + 16384, tid);  // W lo
        stage_E(Et, base_b, kh * 128, smc, tid);
        FENCE_PROXY();
        __syncthreads();
        if (wid == 0 && elect_one_pred()) {
            mma_pass8(tb, dR1, dR2, kh == 0 ? 0u : 1u);
            mma_pass8(tb, dR1, dR3, 1u);
            TCGEN05_COMMIT(sb + SM_MG);
        }
    }
    MBARRIER_WAIT_PARITY(sb + SM_MG, 1);
    TCGEN05_FENCE_AFTER();
    __syncthreads();

    // ------------- A epilogue: TMEM -> A-hi swizzled in R1 ----------------
    {
        u32 a0[32], a1[32];
        TCGEN05_LD_32X32B_X32(a0, tb + chalf * 64);
        TCGEN05_LD_32X32B_X32(a1, tb + chalf * 64 + 32);
        TCGEN05_WAIT_LD();
        u16* hb = (u16*)(smc + SM_R1);
#pragma unroll
        for (int q = 0; q < 8; ++q) {
            int k0 = chalf * 64 + q * 4;
            float v0 = __uint_as_float(a0[4 * q]),     v1 = __uint_as_float(a0[4 * q + 1]);
            float v2 = __uint_as_float(a0[4 * q + 2]), v3 = __uint_as_float(a0[4 * q + 3]);
            *(uint2*)(hb + swz_idx(r_loc, k0)) =
                make_uint2((u32)f2bu(v0) | ((u32)f2bu(v1) << 16),
                           (u32)f2bu(v2) | ((u32)f2bu(v3) << 16));
            int k1 = k0 + 32;
            float w0 = __uint_as_float(a1[4 * q]),     w1 = __uint_as_float(a1[4 * q + 1]);
            float w2 = __uint_as_float(a1[4 * q + 2]), w3 = __uint_as_float(a1[4 * q + 3]);
            *(uint2*)(hb + swz_idx(r_loc, k1)) =
                make_uint2((u32)f2bu(w0) | ((u32)f2bu(w1) << 16),
                           (u32)f2bu(w2) | ((u32)f2bu(w3) << 16));
        }
        if (t == TT - 1) {   // hi/lo split + fp32 for the accuracy pass
            u16* gh = g_A29B + rb * 32768;
            u16* gl = gh + 16384;
#pragma unroll
            for (int j = 0; j < 32; ++j) {
                float v = __uint_as_float(a0[j]);
                int k = chalf * 64 + j;
                u16 hi = f2bu(v);
                gh[swz_idx(r_loc, k)] = hi;
                gl[swz_idx(r_loc, k)] = f2bu(v - b2f(hi));
                g_A29T[(size_t)k * BBN + base_b + r_loc] = v;

                float w = __uint_as_float(a1[j]);
                int kk = k + 32;
                u16 hi2 = f2bu(w);
                gh[swz_idx(r_loc, kk)] = hi2;
                gl[swz_idx(r_loc, kk)] = f2bu(w - b2f(hi2));
                g_A29T[(size_t)kk * BBN + base_b + r_loc] = w;
            }
        }
        TCGEN05_FENCE_BEFORE();
        FENCE_PROXY();
    }

    // ------------- GEMM2: 16 chunks of 128 cols, 1-pass, pipelined --------
    copy32k(smc + SM_R2, g_repB, tid);       // chunk 0 (hi only)
    FENCE_PROXY();
    __syncthreads();
    if (wid == 0 && elect_one_pred()) {
        mma_pass8(tb, dR1, dR2, 0u);         // S chunk0 -> cols 0..127
        TCGEN05_COMMIT(sb + SM_FS0);
    }

    const float NEGINF = __int_as_float(0xff800000);
    float m = NEGINF, s = 0.0f;

    for (int i = 0; i < 16; ++i) {
        int p = i & 1;
        if (i < 15) {   // next chunk's B-hi into the other region
            copy32k(smc + (p ? SM_R2 : SM_R3), g_repB + (i + 1) * 32768, tid);
            FENCE_PROXY();
        }
        MBARRIER_WAIT_PARITY(sb + (p ? SM_FS1 : SM_FS0), (i >> 1) & 1);
        TCGEN05_FENCE_AFTER();
        __syncthreads();
        if (i < 15 && wid == 0 && elect_one_pred()) {
            mma_pass8(tb + 128 * (p ^ 1), dR1, p ? dR2 : dR3, 0u);
            TCGEN05_COMMIT(sb + (p ? SM_FS0 : SM_FS1));
        }

        u32 v0[32], v1[32];
        TCGEN05_LD_32X32B_X32(v0, tb + 128 * p + chalf * 64);
        TCGEN05_LD_32X32B_X32(v1, tb + 128 * p + chalf * 64 + 32);
        TCGEN05_WAIT_LD();

        if (i == rb) {
            int jd = r_loc - chalf * 64;
#pragma unroll
            for (int j = 0; j < 32; ++j) {
                if (j == jd)      sDiag[r_loc] = __uint_as_float(v0[j]);
                if (j + 32 == jd) sDiag[r_loc] = __uint_as_float(v1[j]);
            }
        }

        float lm = NEGINF;
#pragma unroll
        for (int j = 0; j < 32; ++j) {
            lm = fmaxf(lm, __uint_as_float(v0[j]));
            lm = fmaxf(lm, __uint_as_float(v1[j]));
        }
        float nm = fmaxf(m, lm);
        float add = 0.0f;
#pragma unroll
        for (int j = 0; j < 32; ++j) {
            add += __expf(__uint_as_float(v0[j]) - nm);
            add += __expf(__uint_as_float(v1[j]) - nm);
        }
        s = fmaf(s, __expf(m - nm), add);
        m = nm;
        TCGEN05_FENCE_BEFORE();
    }
    __syncthreads();

    sMS[r_loc * 4 + chalf * 2]     = m;
    sMS[r_loc * 4 + chalf * 2 + 1] = s;
    __syncthreads();

    if (tid < 128) {
        float m0 = sMS[tid * 4], s0 = sMS[tid * 4 + 1];
        float m1 = sMS[tid * 4 + 2], s1 = sMS[tid * 4 + 3];
        float mm = fmaxf(m0, m1);
        float ss = s0 * __expf(m0 - mm) + s1 * __expf(m1 - mm);
        float lse = mm + __logf(ss);
        if (t == TT - 1) g_lse29[base_b + tid] = lse;
        float part = sDiag[tid] - lse;
#pragma unroll
        for (int o = 1; o < 32; o <<= 1)
            part += __shfl_xor_sync(0xffffffffu, part, o);
        if ((tid & 31) == 0) sRed[tid >> 5] = part;
    }
    __syncthreads();
    if (tid == 0)
        g_nce[t * 16 + rb] = sRed[0] + sRed[1] + sRed[2] + sRed[3];

    if (tid == 0) {
        MBARRIER_INVAL(sb + SM_MG);
        MBARRIER_INVAL(sb + SM_FS0);
        MBARRIER_INVAL(sb + SM_FS1);
    }
    __syncthreads();
    if (wid == 0) {
        TCGEN05_RELINQ();
        TCGEN05_DEALLOC(tb, 256);
    }
#endif  // USE_TCGEN05 (fallback: no-op; sm_103a cubin is what runs)
}

// ---------------------------------------------------------------------------
// Accuracy pass (t=29) on tensor cores (3-pass split) + fused finalize
// ---------------------------------------------------------------------------
__global__ void __launch_bounds__(256, 1)
k_acc2(float* __restrict__ out, int out_size) {
    extern __shared__ char smc[];
#if USE_TCGEN05
    const u32 sb = smem_to_u32(smc);
    float* sLse = (float*)(smc + SA_LSE);
    int*   sLast = (int*)(smc + SA_LAST);

    const int cb  = blockIdx.x;      // column block (c rows of D)
    const int bb  = blockIdx.y;      // b block (N cols of D)
    const int tid = threadIdx.x;
    const int wid = tid >> 5;
    const int lane = tid & 31;
    const int sub = wid & 3;
    const int chalf = wid >> 2;
    const int r_loc = sub * 32 + lane;

    if (wid == 0) TCGEN05_ALLOC(sb + SA_TMEMPTR, 128);
    if (tid == 0) MBARRIER_INIT(sb + SA_MB, 1);
    __syncthreads();
    u32 tb;
    asm volatile("ld.shared.b32 %0, [%1];" : "=r"(tb) : "r"(sb + SA_TMEMPTR));

    copy32k(smc + SA_RH, g_repB + cb * 32768, tid);
    copy32k(smc + SA_RL, g_repB + cb * 32768 + 16384, tid);
    copy32k(smc + SA_AH, g_A29B + bb * 32768, tid);
    copy32k(smc + SA_AL, g_A29B + bb * 32768 + 16384, tid);
    if (tid < 128) sLse[tid] = g_lse29[bb * 128 + tid];
    FENCE_PROXY();
    __syncthreads();

    if (wid == 0 && elect_one_pred()) {
        u64 dRH = MK_DESC(sb + SA_RH), dRL = MK_DESC(sb + SA_RL);
        u64 dAH = MK_DESC(sb + SA_AH), dAL = MK_DESC(sb + SA_AL);
        mma_pass8(tb, dRH, dAH, 0u);
        mma_pass8(tb, dRH, dAL, 1u);
        mma_pass8(tb, dRL, dAH, 1u);
        TCGEN05_COMMIT(sb + SA_MB);
    }
    MBARRIER_WAIT_PARITY(sb + SA_MB, 0);
    TCGEN05_FENCE_AFTER();

    u32 v0[32], v1[32];
    TCGEN05_LD_32X32B_X32(v0, tb + chalf * 64);
    TCGEN05_LD_32X32B_X32(v1, tb + chalf * 64 + 32);
    TCGEN05_WAIT_LD();

    int c = cb * 128 + r_loc;
    u64 best = 0ULL;
#pragma unroll
    for (int j = 0; j < 32; ++j) {
        float v = __uint_as_float(v0[j]) - sLse[chalf * 64 + j];
        u32 u = __float_as_uint(v);
        u = (u & 0x80000000u) ? ~u : (u | 0x80000000u);
        u64 key = ((u64)u << 32) | (u32)(bb * 128 + chalf * 64 + j);
        if (key > best) best = key;
    }
#pragma unroll
    for (int j = 0; j < 32; ++j) {
        float v = __uint_as_float(v1[j]) - sLse[chalf * 64 + 32 + j];
        u32 u = __float_as_uint(v);
        u = (u & 0x80000000u) ? ~u : (u | 0x80000000u);
        u64 key = ((u64)u << 32) | (u32)(bb * 128 + chalf * 64 + 32 + j);
        if (key > best) best = key;
    }
    atomicMax(&g_win[c], best);

    TCGEN05_FENCE_BEFORE();
    __syncthreads();
    if (tid == 0) MBARRIER_INVAL(sb + SA_MB);
    __syncthreads();
    if (wid == 0) {
        TCGEN05_RELINQ();
        TCGEN05_DEALLOC(tb, 128);
    }

    // ---- fused finalize: last CTA does the reduction + output ----
    __threadfence();
    if (tid == 0) {
        int done = atomicAdd(&g_done, 1);
        *sLast = (done == gridDim.x * gridDim.y - 1);
    }
    __syncthreads();
    if (*sLast) {
        __shared__ double rd[256];
        __shared__ int    ri[256];
        int cnt = 0;
        for (int cc = tid; cc < BBN; cc += 256)
            cnt += ((u32)(g_win[cc] & 0xffffffffULL) == (u32)cc);
        double sum = 0.0;
        for (int i = tid; i < TT * 16; i += 256) sum += (double)g_nce[i];
        rd[tid] = sum; ri[tid] = cnt;
        __syncthreads();
        for (int st = 128; st > 0; st >>= 1) {
            if (tid < st) { rd[tid] += rd[tid + st]; ri[tid] += ri[tid + st]; }
            __syncthreads();
        }
        if (tid == 0) {
            out[0] = (float)ri[0] / (float)BBN;
            out[1] = (float)(rd[0] / (-(double)(BBN * TT)));
            out[2] = (float)BBN;
            out[3] = (float)(BBN * TT);
            for (int i = 4; i < out_size; ++i) out[i] = 0.0f;
            g_done = 0;   // reset for next graph replay
        }
    }
#endif
}

// ---------------------------------------------------------------------------
extern "C" void kernel_launch(void* const* d_in, const int* in_sizes, int n_in,
                              void* d_out, int out_size) {
    const float* E   = (const float*)d_in[0];   // [30, 2048, 256]
    const float* rep = (const float*)d_in[1];   // [2048, 128]
    const float* W   = (const float*)d_in[2];   // [30, 256, 128]
    // d_in[3] = Wk_b: row-constant shift, cancels in both softmaxes
    float* out = (float*)d_out;

    cudaFuncSetAttribute(k_main2, cudaFuncAttributeMaxDynamicSharedMemorySize, SMEM_MAIN);
    cudaFuncSetAttribute(k_acc2,  cudaFuncAttributeMaxDynamicSharedMemorySize, SMEM_ACC2);

    k_pre_rep<<<(BBN * DHH) / 256, 256>>>(rep);
    k_pre_w<<<(TT * DD * DHH) / 256, 256>>>(W);

    dim3 g2(16, TT);
    k_main2<<<g2, 256, SMEM_MAIN>>>(E);

    dim3 g3(16, 16);
    k_acc2<<<g3, 256, SMEM_ACC2>>>(out, out_size);
}

// round 7
// speedup vs baseline: 5.4518x; 1.1908x over previous
#include <cuda_runtime.h>
#include <cuda_bf16.h>
#include <math.h>
#include <cstdint>

#define TT  30
#define BBN 2048
#define DD  256
#define DHH 128

typedef unsigned long long u64;
typedef unsigned int       u32;
typedef unsigned short     u16;

#if defined(__CUDA_ARCH_FEAT_SM103_ALL) || defined(__CUDA_ARCH_FEAT_SM100_ALL) || defined(__CUDA_ARCH_FEAT_SM101_ALL)
#define USE_TCGEN05 1
#else
#define USE_TCGEN05 0
#endif

// Fixed softmax shift 64: overflow needs s>152 (impossible, |S|max ~98);
// FTZ flush-to-zero needs s<-23.3 (those terms are >=55 e-folds below any row
// max -> negligible); an all-zero row sum needs row max < -23.3 (never).
// Clamp makes log(0) structurally impossible regardless.
#define SOFT_SHIFT 64.0f
#define L2E        1.4426950408889634f
#define SHIFT_L2E  (-64.0f * 1.4426950408889634f)

// ---------------------------------------------------------------------------
__device__ float g_lse29[BBN];
__device__ float g_nce[TT * 16];
__device__ u64   g_win[BBN];
__device__ int   g_done = 0;
__device__ u16   g_repB[16 * 32768];       // per 128-col chunk: [hi 16K][lo 16K], swizzled
__device__ u16   g_WB[TT * 2 * 32768];     // per (t,khalf): [hi][lo] W^T tile, swizzled
__device__ u16   g_A29B[16 * 32768];       // per 128-row block: [hi][lo] A29, swizzled

// ---------------------------------------------------------------------------
__device__ __forceinline__ u16 f2bu(float f) {
    __nv_bfloat16 b = __float2bfloat16(f);
    return reinterpret_cast<u16&>(b);
}
__device__ __forceinline__ float b2f(u16 u) {
    __nv_bfloat16 b = reinterpret_cast<__nv_bfloat16&>(u);
    return __bfloat162float(b);
}
__device__ __forceinline__ int swz_idx(int m, int k) {
    int byte = (((m >> 3) + ((k >> 6) << 4)) << 10) + ((m & 7) << 7) + ((k & 63) << 1);
    byte ^= (byte >> 3) & 0x70;
    return byte >> 1;
}
__device__ __forceinline__ float ex2f(float x) {
    float r; asm("ex2.approx.ftz.f32 %0, %1;" : "=f"(r) : "f"(x)); return r;
}

// ---------------------------------------------------------------------------
__global__ void k_pre_rep(const float* __restrict__ rep) {
    int idx = blockIdx.x * blockDim.x + threadIdx.x;   // c*128 + k
    int c = idx >> 7, k = idx & 127;
    float v = rep[idx];
    u16 hi = f2bu(v);
    u16 lo = f2bu(v - b2f(hi));
    int cb = c >> 7, cl = c & 127;
    g_repB[cb * 32768 + swz_idx(cl, k)]         = hi;
    g_repB[cb * 32768 + 16384 + swz_idx(cl, k)] = lo;
    if (idx < BBN) g_win[idx] = 0ULL;
}

__global__ void k_pre_w(const float* __restrict__ W) {
    int idx = blockIdx.x * blockDim.x + threadIdx.x;
    int t = idx / (DD * DHH);
    int r = idx - t * DD * DHH;
    int d = r / DHH, h = r - d * DHH;
    float v = W[idx];
    u16 hi = f2bu(v);
    u16 lo = f2bu(v - b2f(hi));
    int half = d >> 7, kl = d & 127;
    int base = t * 65536 + half * 32768;
    g_WB[base + swz_idx(h, kl)]         = hi;
    g_WB[base + 16384 + swz_idx(h, kl)] = lo;
}

#if USE_TCGEN05
// ===========================================================================
__device__ __forceinline__ u32 elect_one_pred() {
    u32 pred;
    asm volatile("{\n\t.reg .pred p;\n\telect.sync _|p, 0xFFFFFFFF;\n\tselp.b32 %0, 1, 0, p;\n\t}" : "=r"(pred));
    return pred;
}
__device__ __forceinline__ u32 smem_to_u32(const void* p) {
    u32 a;
    asm("{ .reg .u64 t; cvta.to.shared.u64 t, %1; cvt.u32.u64 %0, t; }" : "=r"(a) : "l"(p));
    return a;
}
#define TCGEN05_ALLOC(sa, n) \
    asm volatile("tcgen05.alloc.cta_group::1.sync.aligned.shared::cta.b32 [%0], %1;" :: "r"((u32)(sa)), "r"((u32)(n)) : "memory")
#define TCGEN05_DEALLOC(ta, n) \
    asm volatile("tcgen05.dealloc.cta_group::1.sync.aligned.b32 %0, %1;" :: "r"(ta), "r"((u32)(n)))
#define TCGEN05_RELINQ() \
    asm volatile("tcgen05.relinquish_alloc_permit.cta_group::1.sync.aligned;")
#define TCGEN05_COMMIT(mb) \
    asm volatile("tcgen05.commit.cta_group::1.mbarrier::arrive::one.shared::cluster.b64 [%0];" :: "r"((u32)(mb)) : "memory")
#define TCGEN05_FENCE_BEFORE()  asm volatile("tcgen05.fence::before_thread_sync;" ::: "memory")
#define TCGEN05_FENCE_AFTER()   asm volatile("tcgen05.fence::after_thread_sync;" ::: "memory")
#define TCGEN05_WAIT_LD()       asm volatile("tcgen05.wait::ld.sync.aligned;" ::: "memory")
#define FENCE_PROXY()           asm volatile("fence.proxy.async.shared::cta;" ::: "memory")
#define MBARRIER_INIT(mb, cnt) \
    asm volatile("mbarrier.init.shared.b64 [%0], %1;" :: "r"((u32)(mb)), "r"((u32)(cnt)) : "memory")
#define MBARRIER_INVAL(mb) \
    asm volatile("mbarrier.inval.shared.b64 [%0];" :: "r"((u32)(mb)) : "memory")
#define MBARRIER_WAIT_PARITY(mb, ph) do {                                          \
    u32 _m = (u32)(mb); u32 _p = (u32)(ph); u32 _d;                                \
    asm volatile("{\n\t.reg .pred p;\n\t"                                          \
        "mbarrier.try_wait.parity.acquire.cta.shared::cta.b64 p, [%1], %2;\n\t"    \
        "selp.b32 %0, 1, 0, p;\n\t}" : "=r"(_d) : "r"(_m), "r"(_p) : "memory");    \
    if (!_d) {                                                                     \
        asm volatile("{\n\t.reg .pred P1;\n\t"                                     \
        "WL_%=:\n\t"                                                               \
        "mbarrier.try_wait.parity.acquire.cta.shared::cta.b64 P1, [%0], %1, 0x989680;\n\t" \
        "@P1 bra.uni WD_%=;\n\t"                                                   \
        "bra.uni WL_%=;\n\t"                                                       \
        "WD_%=:\n\t}" :: "r"(_m), "r"(_p) : "memory");                             \
    }                                                                              \
} while (0)

#define TCGEN05_LD_32X32B_X32(r, ta) \
    asm volatile( \
        "tcgen05.ld.sync.aligned.32x32b.x32.b32 " \
        "{%0, %1, %2, %3, %4, %5, %6, %7, " \
        " %8, %9, %10, %11, %12, %13, %14, %15, " \
        " %16, %17, %18, %19, %20, %21, %22, %23, " \
        " %24, %25, %26, %27, %28, %29, %30, %31}, [%32];" \
        : "=r"((r)[0]),  "=r"((r)[1]),  "=r"((r)[2]),  "=r"((r)[3]), \
          "=r"((r)[4]),  "=r"((r)[5]),  "=r"((r)[6]),  "=r"((r)[7]), \
          "=r"((r)[8]),  "=r"((r)[9]),  "=r"((r)[10]), "=r"((r)[11]), \
          "=r"((r)[12]), "=r"((r)[13]), "=r"((r)[14]), "=r"((r)[15]), \
          "=r"((r)[16]), "=r"((r)[17]), "=r"((r)[18]), "=r"((r)[19]), \
          "=r"((r)[20]), "=r"((r)[21]), "=r"((r)[22]), "=r"((r)[23]), \
          "=r"((r)[24]), "=r"((r)[25]), "=r"((r)[26]), "=r"((r)[27]), \
          "=r"((r)[28]), "=r"((r)[29]), "=r"((r)[30]), "=r"((r)[31]) \
        : "r"(ta))

__device__ __forceinline__ void mma_f16_ss(u32 d, u64 ad, u64 bd, u32 idesc, u32 en) {
    asm volatile(
        "{\n\t.reg .pred p;\n\tsetp.ne.u32 p, %5, 0;\n\t"
        "tcgen05.mma.cta_group::1.kind::f16 [%0], %1, %2, %3, {%4, %4, %4, %4}, p;\n\t}"
        :: "r"(d), "l"(ad), "l"(bd), "r"(idesc), "r"(0u), "r"(en) : "memory");
}

static constexpr u64 DESC_BASE =
    (u64(2) << 61) | (u64(1) << 46) | (u64(64) << 32) | (u64(1) << 16);
#define MK_DESC(a) (DESC_BASE | ((u64)((a) >> 4) & 0x3FFF))
#define IDESC 0x8200490u     // F32 accum, BF16xBF16, M=128, N=128

__device__ __forceinline__ void mma_pass8(u32 d, u64 ad, u64 bd, u32 en0) {
#pragma unroll
    for (int j = 0; j < 8; ++j) {
        u64 off = (u64)((j >> 2) * 1024 + (j & 3) * 2);
        mma_f16_ss(d, ad + off, bd + off, IDESC, j == 0 ? en0 : 1u);
    }
}

__device__ __forceinline__ void copy32k(char* dst, const void* src, int tid) {
    const float4* s = (const float4*)src;
    float4* d = (float4*)dst;
#pragma unroll
    for (int i = 0; i < 8; ++i) d[tid + i * 256] = s[tid + i * 256];
}
#endif  // USE_TCGEN05

// ---------------------------------------------------------------------------
#define SM_TMEMPTR 0
#define SM_MG      8
#define SM_FS0     16
#define SM_FS1     24
#define SM_DIAG    64        // 128 f32
#define SM_MS      576       // 256 f32
#define SM_RED     1600      // 4 f32
#define SM_R1      4096      // 32KB: E-hi / A-hi
#define SM_R2      36864     // 32KB
#define SM_R3      69632     // 32KB
#define SMEM_MAIN  102400

#define SA_TMEMPTR 0
#define SA_MB      8
#define SA_LAST    16
#define SA_LSE     64
#define SA_RH      1024
#define SA_RL      33792
#define SA_AH      66560
#define SA_AL      99328
#define SMEM_ACC2  132096

#if USE_TCGEN05
__device__ __forceinline__ void stage_E(const float* __restrict__ Et, int base_b, int dk,
                                        char* smc, int tid) {
    int row = tid >> 1;
    int cs  = (tid & 1) * 64;
    const float4* src = (const float4*)(Et + (size_t)(base_b + row) * DD + dk + cs);
    u16* hb = (u16*)(smc + SM_R1);
#pragma unroll
    for (int q = 0; q < 16; ++q) {
        float4 v = src[q];
        int k = cs + q * 4;
        uint2 hw = make_uint2((u32)f2bu(v.x) | ((u32)f2bu(v.y) << 16),
                              (u32)f2bu(v.z) | ((u32)f2bu(v.w) << 16));
        *(uint2*)(hb + swz_idx(row, k)) = hw;
    }
}
#endif

// ---------------------------------------------------------------------------
// Main fused kernel: one CTA per (t, 128-row block); TMEM layout as R5
// (A at tb+0..127, S ping-pong at tb+128/tb+256), alloc 512, occupancy 1.
// ---------------------------------------------------------------------------
__global__ void __launch_bounds__(256, 1)
k_main2(const float* __restrict__ E) {
    extern __shared__ char smc[];
#if USE_TCGEN05
    const u32 sb = smem_to_u32(smc);
    float* sDiag = (float*)(smc + SM_DIAG);
    float* sMS   = (float*)(smc + SM_MS);
    float* sRed  = (float*)(smc + SM_RED);

    const int t      = blockIdx.y;
    const int rb     = blockIdx.x;
    const int base_b = rb * 128;
    const int tid    = threadIdx.x;
    const int wid    = tid >> 5;
    const int lane   = tid & 31;
    const int sub    = wid & 3;
    const int chalf  = wid >> 2;
    const int r_loc  = sub * 32 + lane;

    const float* Et = E + (size_t)t * BBN * DD;

    if (wid == 0) TCGEN05_ALLOC(sb + SM_TMEMPTR, 512);
    if (tid == 0) {
        MBARRIER_INIT(sb + SM_MG,  1);
        MBARRIER_INIT(sb + SM_FS0, 1);
        MBARRIER_INIT(sb + SM_FS1, 1);
    }
    __syncthreads();
    u32 tb;
    asm volatile("ld.shared.b32 %0, [%1];" : "=r"(tb) : "r"(sb + SM_TMEMPTR));

    const u64 dR1 = MK_DESC(sb + SM_R1);
    const u64 dR2 = MK_DESC(sb + SM_R2);
    const u64 dR3 = MK_DESC(sb + SM_R3);

    // ------------- GEMM1 (2-pass): A = Eh·(Wh+Wl), two K-halves -----------
#pragma unroll
    for (int kh = 0; kh < 2; ++kh) {
        if (kh == 1) MBARRIER_WAIT_PARITY(sb + SM_MG, 0);
        copy32k(smc + SM_R2, g_WB + t * 65536 + kh * 32768, tid);
        copy32k(smc + SM_R3, g_WB + t * 65536 + kh * 32768 + 16384, tid);
        stage_E(Et, base_b, kh * 128, smc, tid);
        FENCE_PROXY();
        __syncthreads();
        if (wid == 0 && elect_one_pred()) {
            mma_pass8(tb, dR1, dR2, kh == 0 ? 0u : 1u);
            mma_pass8(tb, dR1, dR3, 1u);
            TCGEN05_COMMIT(sb + SM_MG);
        }
    }
    MBARRIER_WAIT_PARITY(sb + SM_MG, 1);
    TCGEN05_FENCE_AFTER();
    __syncthreads();

    // ------------- A epilogue: TMEM -> A-hi swizzled in R1 ----------------
    {
        u32 a0[32], a1[32];
        TCGEN05_LD_32X32B_X32(a0, tb + chalf * 64);
        TCGEN05_LD_32X32B_X32(a1, tb + chalf * 64 + 32);
        TCGEN05_WAIT_LD();
        u16* hb = (u16*)(smc + SM_R1);
#pragma unroll
        for (int q = 0; q < 8; ++q) {
            int k0 = chalf * 64 + q * 4;
            float v0 = __uint_as_float(a0[4 * q]),     v1 = __uint_as_float(a0[4 * q + 1]);
            float v2 = __uint_as_float(a0[4 * q + 2]), v3 = __uint_as_float(a0[4 * q + 3]);
            *(uint2*)(hb + swz_idx(r_loc, k0)) =
                make_uint2((u32)f2bu(v0) | ((u32)f2bu(v1) << 16),
                           (u32)f2bu(v2) | ((u32)f2bu(v3) << 16));
            int k1 = k0 + 32;
            float w0 = __uint_as_float(a1[4 * q]),     w1 = __uint_as_float(a1[4 * q + 1]);
            float w2 = __uint_as_float(a1[4 * q + 2]), w3 = __uint_as_float(a1[4 * q + 3]);
            *(uint2*)(hb + swz_idx(r_loc, k1)) =
                make_uint2((u32)f2bu(w0) | ((u32)f2bu(w1) << 16),
                           (u32)f2bu(w2) | ((u32)f2bu(w3) << 16));
        }
        if (t == TT - 1) {
            u16* gh = g_A29B + rb * 32768;
            u16* gl = gh + 16384;
#pragma unroll
            for (int j = 0; j < 32; ++j) {
                float v = __uint_as_float(a0[j]);
                int k = chalf * 64 + j;
                u16 hi = f2bu(v);
                gh[swz_idx(r_loc, k)] = hi;
                gl[swz_idx(r_loc, k)] = f2bu(v - b2f(hi));
                float w = __uint_as_float(a1[j]);
                int kk = k + 32;
                u16 hi2 = f2bu(w);
                gh[swz_idx(r_loc, kk)] = hi2;
                gl[swz_idx(r_loc, kk)] = f2bu(w - b2f(hi2));
            }
        }
        TCGEN05_FENCE_BEFORE();
        FENCE_PROXY();
    }

    // ------------- GEMM2: 16 chunks of 128 cols, fixed-shift softmax ------
    copy32k(smc + SM_R2, g_repB, tid);       // chunk 0 (hi only)
    FENCE_PROXY();
    __syncthreads();
    if (wid == 0 && elect_one_pred()) {
        mma_pass8(tb + 128, dR1, dR2, 0u);   // S chunks live at tb+128/tb+256
        TCGEN05_COMMIT(sb + SM_FS0);
    }

    float acc0 = 0.0f, acc1 = 0.0f, acc2 = 0.0f, acc3 = 0.0f;

    for (int i = 0; i < 16; ++i) {
        int p = i & 1;
        if (i < 15) {
            copy32k(smc + (p ? SM_R2 : SM_R3), g_repB + (i + 1) * 32768, tid);
            FENCE_PROXY();
        }
        MBARRIER_WAIT_PARITY(sb + (p ? SM_FS1 : SM_FS0), (i >> 1) & 1);
        TCGEN05_FENCE_AFTER();
        __syncthreads();
        if (i < 15 && wid == 0 && elect_one_pred()) {
            mma_pass8(tb + 128 + 128 * (p ^ 1), dR1, p ? dR2 : dR3, 0u);
            TCGEN05_COMMIT(sb + (p ? SM_FS0 : SM_FS1));
        }

        u32 v0[32], v1[32];
        TCGEN05_LD_32X32B_X32(v0, tb + 128 + 128 * p + chalf * 64);
        TCGEN05_LD_32X32B_X32(v1, tb + 128 + 128 * p + chalf * 64 + 32);
        TCGEN05_WAIT_LD();

        if (i == rb) {   // diagonal capture
            int jd = r_loc - chalf * 64;
#pragma unroll
            for (int j = 0; j < 32; ++j) {
                if (j == jd)      sDiag[r_loc] = __uint_as_float(v0[j]);
                if (j + 32 == jd) sDiag[r_loc] = __uint_as_float(v1[j]);
            }
        }

        // sum += exp(s - 64) via ex2(fma(s, log2e, -64*log2e)); 4-way chains
#pragma unroll
        for (int j = 0; j < 32; j += 4) {
            acc0 += ex2f(fmaf(__uint_as_float(v0[j]),     L2E, SHIFT_L2E));
            acc1 += ex2f(fmaf(__uint_as_float(v0[j + 1]), L2E, SHIFT_L2E));
            acc2 += ex2f(fmaf(__uint_as_float(v0[j + 2]), L2E, SHIFT_L2E));
            acc3 += ex2f(fmaf(__uint_as_float(v0[j + 3]), L2E, SHIFT_L2E));
        }
#pragma unroll
        for (int j = 0; j < 32; j += 4) {
            acc0 += ex2f(fmaf(__uint_as_float(v1[j]),     L2E, SHIFT_L2E));
            acc1 += ex2f(fmaf(__uint_as_float(v1[j + 1]), L2E, SHIFT_L2E));
            acc2 += ex2f(fmaf(__uint_as_float(v1[j + 2]), L2E, SHIFT_L2E));
            acc3 += ex2f(fmaf(__uint_as_float(v1[j + 3]), L2E, SHIFT_L2E));
        }
        TCGEN05_FENCE_BEFORE();
    }
    __syncthreads();

    sMS[r_loc * 2 + chalf] = (acc0 + acc1) + (acc2 + acc3);
    __syncthreads();

    if (tid < 128) {
        float sum = fmaxf(sMS[tid * 2] + sMS[tid * 2 + 1], 1e-35f);
        float lse = SOFT_SHIFT + __logf(sum);
        if (t == TT - 1) g_lse29[base_b + tid] = lse;
        float part = sDiag[tid] - lse;
#pragma unroll
        for (int o = 1; o < 32; o <<= 1)
            part += __shfl_xor_sync(0xffffffffu, part, o);
        if ((tid & 31) == 0) sRed[tid >> 5] = part;
    }
    __syncthreads();
    if (tid == 0)
        g_nce[t * 16 + rb] = sRed[0] + sRed[1] + sRed[2] + sRed[3];

    if (tid == 0) {
        MBARRIER_INVAL(sb + SM_MG);
        MBARRIER_INVAL(sb + SM_FS0);
        MBARRIER_INVAL(sb + SM_FS1);
    }
    __syncthreads();
    if (wid == 0) {
        TCGEN05_RELINQ();
        TCGEN05_DEALLOC(tb, 512);
    }
#endif
}

// ---------------------------------------------------------------------------
// Accuracy pass (t=29) on tensor cores + fused finalize  (unchanged, proven)
// ---------------------------------------------------------------------------
__global__ void __launch_bounds__(256, 1)
k_acc2(float* __restrict__ out, int out_size) {
    extern __shared__ char smc[];
#if USE_TCGEN05
    const u32 sb = smem_to_u32(smc);
    float* sLse = (float*)(smc + SA_LSE);
    int*   sLast = (int*)(smc + SA_LAST);

    const int cb  = blockIdx.x;
    const int bb  = blockIdx.y;
    const int tid = threadIdx.x;
    const int wid = tid >> 5;
    const int lane = tid & 31;
    const int sub = wid & 3;
    const int chalf = wid >> 2;
    const int r_loc = sub * 32 + lane;

    if (wid == 0) TCGEN05_ALLOC(sb + SA_TMEMPTR, 128);
    if (tid == 0) MBARRIER_INIT(sb + SA_MB, 1);
    __syncthreads();
    u32 tb;
    asm volatile("ld.shared.b32 %0, [%1];" : "=r"(tb) : "r"(sb + SA_TMEMPTR));

    copy32k(smc + SA_RH, g_repB + cb * 32768, tid);
    copy32k(smc + SA_RL, g_repB + cb * 32768 + 16384, tid);
    copy32k(smc + SA_AH, g_A29B + bb * 32768, tid);
    copy32k(smc + SA_AL, g_A29B + bb * 32768 + 16384, tid);
    if (tid < 128) sLse[tid] = g_lse29[bb * 128 + tid];
    FENCE_PROXY();
    __syncthreads();

    if (wid == 0 && elect_one_pred()) {
        u64 dRH = MK_DESC(sb + SA_RH), dRL = MK_DESC(sb + SA_RL);
        u64 dAH = MK_DESC(sb + SA_AH), dAL = MK_DESC(sb + SA_AL);
        mma_pass8(tb, dRH, dAH, 0u);
        mma_pass8(tb, dRH, dAL, 1u);
        mma_pass8(tb, dRL, dAH, 1u);
        TCGEN05_COMMIT(sb + SA_MB);
    }
    MBARRIER_WAIT_PARITY(sb + SA_MB, 0);
    TCGEN05_FENCE_AFTER();

    u32 v0[32], v1[32];
    TCGEN05_LD_32X32B_X32(v0, tb + chalf * 64);
    TCGEN05_LD_32X32B_X32(v1, tb + chalf * 64 + 32);
    TCGEN05_WAIT_LD();

    int c = cb * 128 + r_loc;
    u64 best = 0ULL;
#pragma unroll
    for (int j = 0; j < 32; ++j) {
        float v = __uint_as_float(v0[j]) - sLse[chalf * 64 + j];
        u32 u = __float_as_uint(v);
        u = (u & 0x80000000u) ? ~u : (u | 0x80000000u);
        u64 key = ((u64)u << 32) | (u32)(bb * 128 + chalf * 64 + j);
        if (key > best) best = key;
    }
#pragma unroll
    for (int j = 0; j < 32; ++j) {
        float v = __uint_as_float(v1[j]) - sLse[chalf * 64 + 32 + j];
        u32 u = __float_as_uint(v);
        u = (u & 0x80000000u) ? ~u : (u | 0x80000000u);
        u64 key = ((u64)u << 32) | (u32)(bb * 128 + chalf * 64 + 32 + j);
        if (key > best) best = key;
    }
    atomicMax(&g_win[c], best);

    TCGEN05_FENCE_BEFORE();
    __syncthreads();
    if (tid == 0) MBARRIER_INVAL(sb + SA_MB);
    __syncthreads();
    if (wid == 0) {
        TCGEN05_RELINQ();
        TCGEN05_DEALLOC(tb, 128);
    }

    __threadfence();
    if (tid == 0) {
        int done = atomicAdd(&g_done, 1);
        *sLast = (done == gridDim.x * gridDim.y - 1);
    }
    __syncthreads();
    if (*sLast) {
        __shared__ double rd[256];
        __shared__ int    ri[256];
        int cnt = 0;
        for (int cc = tid; cc < BBN; cc += 256)
            cnt += ((u32)(g_win[cc] & 0xffffffffULL) == (u32)cc);
        double sum = 0.0;
        for (int i = tid; i < TT * 16; i += 256) sum += (double)g_nce[i];
        rd[tid] = sum; ri[tid] = cnt;
        __syncthreads();
        for (int st = 128; st > 0; st >>= 1) {
            if (tid < st) { rd[tid] += rd[tid + st]; ri[tid] += ri[tid + st]; }
            __syncthreads();
        }
        if (tid == 0) {
            out[0] = (float)ri[0] / (float)BBN;
            out[1] = (float)(rd[0] / (-(double)(BBN * TT)));
            out[2] = (float)BBN;
            out[3] = (float)(BBN * TT);
            for (int i = 4; i < out_size; ++i) out[i] = 0.0f;
            g_done = 0;
        }
    }
#endif
}

// ---------------------------------------------------------------------------
extern "C" void kernel_launch(void* const* d_in, const int* in_sizes, int n_in,
                              void* d_out, int out_size) {
    const float* E   = (const float*)d_in[0];
    const float* rep = (const float*)d_in[1];
    const float* W   = (const float*)d_in[2];
    // d_in[3] = Wk_b: row-constant shift, cancels in both softmaxes
    float* out = (float*)d_out;

    cudaFuncSetAttribute(k_main2, cudaFuncAttributeMaxDynamicSharedMemorySize, SMEM_MAIN);
    cudaFuncSetAttribute(k_acc2,  cudaFuncAttributeMaxDynamicSharedMemorySize, SMEM_ACC2);

    k_pre_rep<<<(BBN * DHH) / 256, 256>>>(rep);
    k_pre_w<<<(TT * DD * DHH) / 256, 256>>>(W);

    dim3 g2(16, TT);
    k_main2<<<g2, 256, SMEM_MAIN>>>(E);

    dim3 g3(16, 16);
    k_acc2<<<g3, 256, SMEM_ACC2>>>(out, out_size);
}